// round 12
// baseline (speedup 1.0000x reference)
#include <cuda_runtime.h>
#include <cuda_bf16.h>

#define BB 2
#define NN 4096
#define CC 128
#define CIN 64
#define KK 16
#define GG 8
#define PPB (NN*KK)       // 65536 positions per batch
#define PP (BB*PPB)       // 131072 positions per cross
#define POS (2*PP)        // merged cross1+cross2 position axis
#define EPSF 1e-5f
#define CNTF 1048576.0f   // 16 * 4096 * 16 elements per (cross,b,g)
#define UPITCH 136        // smem pair-row pitch (uint32), conflict-free
#define STW (2*BB*GG*2)   // stats floats per stage (2 crosses x B x G x 2)

// ---------------- scratch (device globals; no allocs allowed) ----------------
__device__ float g_f1T[BB*NN*CC];
__device__ float g_f2T[BB*NN*CC];
__device__ float g_g1T[BB*NN*CC];
__device__ float g_g2T[BB*NN*CC];
__device__ float g_fn1T[BB*NN*CC];
__device__ float g_fn2T[BB*NN*CC];
__device__ int   g_idx12[BB*NN*KK];
__device__ int   g_idx21[BB*NN*KK];
__device__ float g_dir12[BB*NN*KK*3];
__device__ float g_dir21[BB*NN*KK*3];
__device__ float g_bufA[CC*POS];     // channel-major [c][cross*PP + p]
__device__ float g_bufB[CC*POS];
__device__ float g_stats[5*STW];     // per-stage (sum, sumsq)
__device__ unsigned g_Wh[3*64*128];  // packed bf16-hi pairs: [mat][kpair][orow]
__device__ unsigned g_Wl[3*64*128];  // packed bf16-lo pairs

// ---------------- helpers ----------------------------------------------------
__device__ __forceinline__ void bf16split(float v, unsigned short &h, unsigned short &l){
    __nv_bfloat16 hb = __float2bfloat16_rn(v);
    float hf = __bfloat162float(hb);
    __nv_bfloat16 lb = __float2bfloat16_rn(v - hf);
    h = *(unsigned short*)&hb;
    l = *(unsigned short*)&lb;
}
__device__ __forceinline__ unsigned pack2(unsigned short lo, unsigned short hi){
    return (unsigned)lo | ((unsigned)hi << 16);
}
__device__ __forceinline__ void mma16(float* d, const unsigned* a, unsigned b0, unsigned b1){
    asm("mma.sync.aligned.m16n8k16.row.col.f32.bf16.bf16.f32 "
        "{%0,%1,%2,%3},{%4,%5,%6,%7},{%8,%9},{%0,%1,%2,%3};"
        : "+f"(d[0]),"+f"(d[1]),"+f"(d[2]),"+f"(d[3])
        : "r"(a[0]),"r"(a[1]),"r"(a[2]),"r"(a[3]), "r"(b0),"r"(b1));
}

// -------- input 1x1 convs (+ stats zeroing folded into block 0) --------------
__global__ void k_conv1d_in(const float* __restrict__ feat1, const float* __restrict__ feat2,
                            const float* __restrict__ t11_w, const float* __restrict__ t11_b,
                            const float* __restrict__ t22_w, const float* __restrict__ t22_b,
                            float* __restrict__ stats) {
    if (blockIdx.x==0 && blockIdx.y==0 && blockIdx.z==0){
        for (int l=threadIdx.x; l<5*STW; l+=128) stats[l] = 0.f;
    }
    int job = blockIdx.z;
    int b = blockIdx.y;
    int n0 = blockIdx.x * 32;
    const float* x    = (job==0||job==3) ? feat1 : feat2;
    const float* w    = (job==0||job==2) ? t11_w : t22_w;
    const float* bias = (job==0||job==2) ? t11_b : t22_b;
    float* outp = (job==0) ? g_f1T : (job==1) ? g_f2T : (job==2) ? g_g1T : g_g2T;

    __shared__ float xs[CIN*33];
    int t = threadIdx.x;   // 128
    for (int l=t; l<CIN*32; l+=128) {
        int c=l>>5, j=l&31;
        xs[c*33+j] = x[(b*CIN+c)*NN + n0+j];
    }
    __syncthreads();
    int o = t;
    float wr[CIN];
#pragma unroll
    for (int c=0;c<CIN;c++) wr[c] = w[o*CIN+c];
    float bv = bias[o];
    for (int j=0;j<32;j++){
        float acc = bv;
#pragma unroll
        for (int c=0;c<CIN;c++) acc += wr[c]*xs[c*33+j];
        outp[(b*NN+n0+j)*CC + o] = acc;
    }
}

// ------- KNN (k=16): warp-granular 4-way candidate split + smem merge --------
__global__ void __launch_bounds__(128) k_knn(const float* __restrict__ pc1, const float* __restrict__ pc2) {
    int dir = blockIdx.z;
    const float* pq   = (dir==0) ? pc1 : pc2;
    const float* pcnd = (dir==0) ? pc2 : pc1;
    int*   idxo = (dir==0) ? g_idx12 : g_idx21;
    float* diro = (dir==0) ? g_dir12 : g_dir21;
    int b = blockIdx.y;
    int t = threadIdx.x;
    int q  = t >> 5;        // warp = candidate quarter
    int qi = t & 31;        // query within block (same across warps)
    int n = blockIdx.x*32 + qi;

    float qx = pq[(b*3+0)*NN+n], qy = pq[(b*3+1)*NN+n], qz = pq[(b*3+2)*NN+n];
    float s1 = qx*qx + qy*qy + qz*qz;

    float bd[KK]; int bi[KK];
#pragma unroll
    for (int k=0;k<KK;k++){ bd[k]=1e30f; bi[k]=0; }
    float worst = 1e30f;

    __shared__ float4 sc[1024];
    __shared__ float md[3*32*17];
    __shared__ int   mi[3*32*17];

    for (int r=0; r<4; r++) {
        __syncthreads();
        for (int i=t; i<1024; i+=128) {
            int hs = i >> 8;
            int m = hs*1024 + r*256 + (i & 255);
            float x = pcnd[(b*3+0)*NN+m];
            float y = pcnd[(b*3+1)*NN+m];
            float z = pcnd[(b*3+2)*NN+m];
            sc[i] = make_float4(x,y,z, x*x+y*y+z*z);
        }
        __syncthreads();
        int mbase = q*1024 + r*256;
        const float4* base = &sc[q*256];
#pragma unroll 4
        for (int i=0;i<256;i++) {
            float4 c = base[i];            // warp-broadcast read
            float d = s1 + c.w - 2.f*(qx*c.x + qy*c.y + qz*c.z);
            if (d < worst) {
                int miv = mbase + i;
                float nb[KK]; int ni[KK];
                bool c0 = bd[0] <= d;
                nb[0] = c0 ? bd[0] : d;
                ni[0] = c0 ? bi[0] : miv;
#pragma unroll
                for (int j=1;j<KK;j++){
                    bool cj  = bd[j]   <= d;
                    bool cjm = bd[j-1] <= d;
                    nb[j] = cj ? bd[j] : (cjm ? d : bd[j-1]);
                    ni[j] = cj ? bi[j] : (cjm ? miv : bi[j-1]);
                }
#pragma unroll
                for (int j=0;j<KK;j++){ bd[j]=nb[j]; bi[j]=ni[j]; }
                worst = bd[KK-1];
            }
        }
    }
    __syncthreads();
    if (q > 0){
#pragma unroll
        for (int k=0;k<KK;k++){
            md[((q-1)*32+qi)*17+k] = bd[k];
            mi[((q-1)*32+qi)*17+k] = bi[k];
        }
    }
    __syncthreads();
    if (q == 0){
        for (int s=0;s<3;s++){
#pragma unroll
            for (int k=0;k<KK;k++){
                float d = md[(s*32+qi)*17+k];
                if (d < worst){
                    int miv = mi[(s*32+qi)*17+k];
                    float nb[KK]; int ni[KK];
                    bool c0 = bd[0] <= d;
                    nb[0] = c0 ? bd[0] : d;
                    ni[0] = c0 ? bi[0] : miv;
#pragma unroll
                    for (int j=1;j<KK;j++){
                        bool cj  = bd[j]   <= d;
                        bool cjm = bd[j-1] <= d;
                        nb[j] = cj ? bd[j] : (cjm ? d : bd[j-1]);
                        ni[j] = cj ? bi[j] : (cjm ? miv : bi[j-1]);
                    }
#pragma unroll
                    for (int j=0;j<KK;j++){ bd[j]=nb[j]; bi[j]=ni[j]; }
                    worst = bd[KK-1];
                }
            }
        }
#pragma unroll
        for (int k=0;k<KK;k++){
            int m = bi[k];
            idxo[(b*NN+n)*KK+k] = m;
            float dx = pcnd[(b*3+0)*NN+m] - qx;
            float dy = pcnd[(b*3+1)*NN+m] - qy;
            float dz = pcnd[(b*3+2)*NN+m] - qz;
            diro[((b*NN+n)*KK+k)*3+0] = dx;
            diro[((b*NN+n)*KK+k)*3+1] = dy;
            diro[((b*NN+n)*KK+k)*3+2] = dz;
        }
    }
}

// -------- gather prologue (merged crosses; tail blocks pack weights) ---------
__global__ void k_gather(const int* __restrict__ idxA, const float* __restrict__ dirA,
                         const float* __restrict__ p1A, const float* __restrict__ p2A,
                         const int* __restrict__ idxB, const float* __restrict__ dirB,
                         const float* __restrict__ p1B, const float* __restrict__ p2B,
                         const float* __restrict__ pos_w, const float* __restrict__ pos_b,
                         float* __restrict__ X, float* __restrict__ stats,
                         const float* __restrict__ m1a, const float* __restrict__ m1b,
                         const float* __restrict__ m2a) {
    if (blockIdx.x >= NN/8){
        int j = blockIdx.z*BB + blockIdx.y;
        if (j < 3){
            const float* src = (j==0) ? m1a : (j==1) ? m1b : m2a;
            unsigned* dh = g_Wh + j*64*128;
            unsigned* dl = g_Wl + j*64*128;
            for (int l=threadIdx.x; l<64*128; l+=128){
                int kp = l >> 7, m = l & 127;
                unsigned short h0,l0,h1,l1;
                bf16split(src[m*CC + 2*kp],     h0, l0);
                bf16split(src[m*CC + 2*kp + 1], h1, l1);
                dh[l] = pack2(h0, h1);
                dl[l] = pack2(l0, l1);
            }
        }
        return;
    }
    int cross = blockIdx.z;
    const int*   idx  = cross ? idxB : idxA;
    const float* dirv = cross ? dirB : dirA;
    const float* p1T  = cross ? p1B : p1A;
    const float* p2T  = cross ? p2B : p2A;
    int b = blockIdx.y, n0 = blockIdx.x*8, c = threadIdx.x;
    float pw0 = pos_w[c*3+0], pw1 = pos_w[c*3+1], pw2 = pos_w[c*3+2], pb = pos_b[c];
    __shared__ float sh[CC*33];
    float sum=0.f, sq=0.f;
    int pbase = cross*PP + b*PPB + n0*KK;
    int lane = threadIdx.x & 31, r0 = threadIdx.x >> 5;

    for (int half=0; half<4; half++){
        for (int nn=0; nn<2; nn++){
            int n = n0 + half*2 + nn;
            float p1v = p1T[(b*NN+n)*CC + c];
            const int* ip = &idx[(b*NN+n)*KK];
            const float* dp0 = &dirv[(b*NN+n)*KK*3];
            for (int k=0;k<KK;k++){
                int m = ip[k];
                float pf = pw0*dp0[k*3+0] + pw1*dp0[k*3+1] + pw2*dp0[k*3+2] + pb;
                float v = p2T[(b*NN+m)*CC + c] + p1v + pf;
                sum += v; sq += v*v;
                sh[c*33 + nn*KK + k] = v;
            }
        }
        __syncthreads();
        int po = pbase + half*32;
        for (int r=r0; r<CC; r+=4)
            X[(size_t)r*POS + po + lane] = sh[r*33 + lane];
        __syncthreads();
    }
#pragma unroll
    for (int off=8; off; off>>=1){
        sum += __shfl_down_sync(0xffffffffu, sum, off, 16);
        sq  += __shfl_down_sync(0xffffffffu, sq,  off, 16);
    }
    if ((threadIdx.x & 15)==0){
        int g = c >> 4;
        int slot = (cross*BB + b)*GG + g;
        atomicAdd(&stats[slot*2+0], sum);
        atomicAdd(&stats[slot*2+1], sq);
    }
}

// ---- fused GN+LReLU(load) -> bf16 3-term mma GEMM (32-pair staging) ---------
// Only 3 __syncthreads in the whole kernel: long uninterrupted mma streams.
__global__ void __launch_bounds__(256) k_gemm(const float* __restrict__ X,
        const unsigned* __restrict__ Whp, const unsigned* __restrict__ Wlp,
        const float* __restrict__ bias,
        const float* __restrict__ statsIn, const float* __restrict__ gamma,
        const float* __restrict__ beta, float* __restrict__ Y,
        float* __restrict__ statsOut) {
    __shared__ unsigned Xh[32*UPITCH], Xl[32*UPITCH];
    __shared__ float2 ssS[CC];

    int t = threadIdx.x;
    int pbase = blockIdx.x * 128;
    int cross = pbase >> 17;
    int b = (pbase >> 16) & 1;
    int slotB = (cross*BB + b)*GG;
    if (t < CC) {
        int g = t >> 4;
        float s = statsIn[(slotB+g)*2+0], q = statsIn[(slotB+g)*2+1];
        float mu = s / CNTF;
        float var = q / CNTF - mu*mu;
        float rstd = rsqrtf(var + EPSF);
        float scale = rstd * gamma[t];
        ssS[t] = make_float2(scale, beta[t] - mu*scale);
    }
    __syncthreads();

    int lane = t & 31, w = t >> 5;
    int gid = lane >> 2, tig = lane & 3;
    int om = (w & 3) * 32;      // warp M (output-channel) base
    int pn = (w >> 2) * 64;     // warp N (position) base within the 128 tile

    float acc[2][8][4];
#pragma unroll
    for (int i=0;i<2;i++)
#pragma unroll
        for (int j=0;j<8;j++)
#pragma unroll
            for (int r=0;r<4;r++) acc[i][j][r]=0.f;

    for (int half=0; half<2; half++) {
        if (half) __syncthreads();   // protect smem reuse
        // stage 32 k-pairs (64 k) of X: per thread 16 (k2,col) slots
#pragma unroll
        for (int i=0;i<16;i++){
            int l = t + i*256;          // 0..4095
            int k2 = l>>7, col = l&127;
            int kk = (half*32 + k2)*2;
            float2 s0 = ssS[kk], s1 = ssS[kk+1];
            float x0 = X[(size_t)kk*POS + pbase + col]*s0.x + s0.y;
            float x1 = X[(size_t)(kk+1)*POS + pbase + col]*s1.x + s1.y;
            x0 = (x0>=0.f) ? x0 : 0.1f*x0;
            x1 = (x1>=0.f) ? x1 : 0.1f*x1;
            unsigned short h0,l0,h1,l1;
            bf16split(x0, h0, l0);
            bf16split(x1, h1, l1);
            Xh[k2*UPITCH+col] = pack2(h0, h1);
            Xl[k2*UPITCH+col] = pack2(l0, l1);
        }
        __syncthreads();

        // 4 sub-chunks of 8 k-pairs, no barriers in between
#pragma unroll
        for (int c4=0;c4<4;c4++){
            int kc8 = half*32 + c4*8;   // global k-pair base (weights)
            int lb  = c4*8;             // local staged pair base
            unsigned ah[2][4], al[2][4];
#pragma unroll
            for (int tm=0;tm<2;tm++){
                int mrow = om + tm*16 + gid;
                const unsigned* wh0 = &Whp[(kc8+tig)*128];
                const unsigned* wh4 = &Whp[(kc8+tig+4)*128];
                const unsigned* wl0 = &Wlp[(kc8+tig)*128];
                const unsigned* wl4 = &Wlp[(kc8+tig+4)*128];
                ah[tm][0] = __ldg(wh0 + mrow);
                ah[tm][1] = __ldg(wh0 + mrow + 8);
                ah[tm][2] = __ldg(wh4 + mrow);
                ah[tm][3] = __ldg(wh4 + mrow + 8);
                al[tm][0] = __ldg(wl0 + mrow);
                al[tm][1] = __ldg(wl0 + mrow + 8);
                al[tm][2] = __ldg(wl4 + mrow);
                al[tm][3] = __ldg(wl4 + mrow + 8);
            }
#pragma unroll
            for (int tn=0;tn<8;tn++){
                int p = pn + tn*8 + gid;
                unsigned bh0 = Xh[(lb+tig)*UPITCH + p];
                unsigned bh1 = Xh[(lb+tig+4)*UPITCH + p];
                unsigned bl0 = Xl[(lb+tig)*UPITCH + p];
                unsigned bl1 = Xl[(lb+tig+4)*UPITCH + p];
                // interleave terms across tm: same-acc mmas are 2 apart
                mma16(acc[0][tn], ah[0], bh0, bh1);
                mma16(acc[1][tn], ah[1], bh0, bh1);
                mma16(acc[0][tn], al[0], bh0, bh1);
                mma16(acc[1][tn], al[1], bh0, bh1);
                mma16(acc[0][tn], ah[0], bl0, bl1);
                mma16(acc[1][tn], ah[1], bl0, bl1);
            }
        }
    }

    // epilogue: bias, stores, GN stats
    float ssum[2] = {0.f, 0.f}, sq[2] = {0.f, 0.f};
#pragma unroll
    for (int tm=0;tm<2;tm++){
        int row0 = om + tm*16 + gid;
        float bv0 = bias[row0], bv1 = bias[row0+8];
#pragma unroll
        for (int tn=0;tn<8;tn++){
            float y0 = acc[tm][tn][0] + bv0;
            float y1 = acc[tm][tn][1] + bv0;
            float y2 = acc[tm][tn][2] + bv1;
            float y3 = acc[tm][tn][3] + bv1;
            ssum[tm] += (y0+y1)+(y2+y3);
            sq[tm]   += (y0*y0+y1*y1)+(y2*y2+y3*y3);
            int col = pbase + pn + tn*8 + tig*2;
            *(float2*)&Y[(size_t)row0*POS + col]     = make_float2(y0,y1);
            *(float2*)&Y[(size_t)(row0+8)*POS + col] = make_float2(y2,y3);
        }
    }
#pragma unroll
    for (int off=16; off; off>>=1){
        ssum[0] += __shfl_down_sync(0xffffffffu, ssum[0], off);
        sq[0]   += __shfl_down_sync(0xffffffffu, sq[0],   off);
        ssum[1] += __shfl_down_sync(0xffffffffu, ssum[1], off);
        sq[1]   += __shfl_down_sync(0xffffffffu, sq[1],   off);
    }
    if (lane == 0){
        int gb = (w & 3)*2;
        atomicAdd(&statsOut[(slotB+gb)*2+0],   ssum[0]);
        atomicAdd(&statsOut[(slotB+gb)*2+1],   sq[0]);
        atomicAdd(&statsOut[(slotB+gb+1)*2+0], ssum[1]);
        atomicAdd(&statsOut[(slotB+gb+1)*2+1], sq[1]);
    }
}

// ---- fused GN+LReLU + max-pool + trailing 1x1 conv (crosses 1/2) ------------
__global__ void __launch_bounds__(128) k_poolconv(const float* __restrict__ Y,
                          const float* __restrict__ statsIn,
                          const float* __restrict__ gamma, const float* __restrict__ beta,
                          const float* __restrict__ t1_w, const float* __restrict__ t1_b,
                          const float* __restrict__ t2_w, const float* __restrict__ t2_b,
                          float* __restrict__ outBase, float* __restrict__ fn1T,
                          float* __restrict__ fn2T) {
    int cross = blockIdx.z;
    int b = blockIdx.y;
    int t = threadIdx.x;
    int n0 = blockIdx.x*32;
    int p0 = cross*PP + b*PPB + n0*KK;      // 512 positions
    const float* w    = cross ? t2_w : t1_w;
    const float* bias = cross ? t2_b : t1_b;
    float* outCM = outBase + (size_t)cross*BB*CC*NN;
    float* fnT   = cross ? fn2T : fn1T;
    int slotB = (cross*BB + b)*GG;

    __shared__ float2 ssS[CC];
    __shared__ float xs[CC*36];
    if (t < CC){
        int g = t >> 4;
        float s = statsIn[(slotB+g)*2+0], q = statsIn[(slotB+g)*2+1];
        float mu = s / CNTF;
        float var = q / CNTF - mu*mu;
        float rstd = rsqrtf(var + EPSF);
        float scale = rstd * gamma[t];
        ssS[t] = make_float2(scale, beta[t] - mu*scale);
    }
    __syncthreads();

    int kk = t & 15;
#pragma unroll 2
    for (int c=0;c<CC;c++){
        float2 ss = ssS[c];
        const float* yrow = &Y[(size_t)c*POS + p0];
#pragma unroll
        for (int j=0;j<4;j++){
            float v = yrow[t + j*128]*ss.x + ss.y;
            v = (v>=0.f) ? v : 0.1f*v;
#pragma unroll
            for (int off=8; off; off>>=1)
                v = fmaxf(v, __shfl_xor_sync(0xffffffffu, v, off, 16));
            if (kk == 0) xs[c*36 + ((t + j*128)>>4)] = v;
        }
    }
    __syncthreads();

    int o = t;
    float acc[32];
    float bv = bias[o];
#pragma unroll
    for (int j=0;j<32;j++) acc[j]=bv;
    for (int cc=0; cc<4; cc++){
        float wr[32];
#pragma unroll
        for (int c2=0;c2<32;c2++) wr[c2] = w[o*CC + cc*32 + c2];
#pragma unroll
        for (int c2=0;c2<32;c2++){
            const float* xrow = &xs[(cc*32+c2)*36];
            float wv = wr[c2];
#pragma unroll
            for (int j4=0;j4<8;j4++){
                float4 xv = *(const float4*)&xrow[j4*4];
                acc[j4*4+0]+=wv*xv.x; acc[j4*4+1]+=wv*xv.y;
                acc[j4*4+2]+=wv*xv.z; acc[j4*4+3]+=wv*xv.w;
            }
        }
    }
#pragma unroll
    for (int j=0;j<32;j++) fnT[(b*NN+n0+j)*CC + o] = acc[j];
    __syncthreads();
#pragma unroll
    for (int j=0;j<32;j++) xs[o*36+j] = acc[j];
    __syncthreads();
    int lane = t & 31, r0 = t >> 5;
    for (int r=r0; r<CC; r+=4)
        outCM[(b*CC+r)*NN + n0 + lane] = xs[r*36+lane];
}

// ------- GN+LReLU apply + max-pool over K (cross3 epilogue) ------------------
__global__ void __launch_bounds__(128) k_pool(const float* __restrict__ Y,
                       const float* __restrict__ statsIn,
                       const float* __restrict__ gamma, const float* __restrict__ beta,
                       float* __restrict__ outCM) {
    int b = blockIdx.y;
    int t = threadIdx.x;
    int p0 = b*PPB + blockIdx.x*128;
    int nb = blockIdx.x*8 + (t >> 4);
    int kk = t & 15;
    int slotB = b*GG;
    __shared__ float2 ssS[CC];
    if (t < CC){
        int g = t >> 4;
        float s = statsIn[(slotB+g)*2+0], q = statsIn[(slotB+g)*2+1];
        float mu = s / CNTF;
        float var = q / CNTF - mu*mu;
        float rstd = rsqrtf(var + EPSF);
        float scale = rstd * gamma[t];
        ssS[t] = make_float2(scale, beta[t] - mu*scale);
    }
    __syncthreads();
#pragma unroll 4
    for (int c=0;c<CC;c++){
        float2 ss = ssS[c];
        float v = Y[(size_t)c*POS + p0 + t]*ss.x + ss.y;
        v = (v>=0.f) ? v : 0.1f*v;
#pragma unroll
        for (int off=8; off; off>>=1)
            v = fmaxf(v, __shfl_xor_sync(0xffffffffu, v, off, 16));
        if (kk == 0)
            outCM[(b*CC+c)*NN + nb] = v;
    }
}

// ---------------- host orchestration ----------------------------------------
extern "C" void kernel_launch(void* const* d_in, const int* in_sizes, int n_in,
                              void* d_out, int out_size) {
    const float* pc1     = (const float*)d_in[0];
    const float* pc2     = (const float*)d_in[1];
    const float* feat1   = (const float*)d_in[2];
    const float* feat2   = (const float*)d_in[3];
    const float* t11_w   = (const float*)d_in[4];
    const float* t11_b   = (const float*)d_in[5];
    const float* t22_w   = (const float*)d_in[6];
    const float* t22_b   = (const float*)d_in[7];
    const float* pos1_w  = (const float*)d_in[8];
    const float* pos1_b  = (const float*)d_in[9];
    const float* gn1_g   = (const float*)d_in[10];
    const float* gn1_b   = (const float*)d_in[11];
    const float* m1a_w   = (const float*)d_in[12];
    const float* m1a_b   = (const float*)d_in[13];
    const float* m1a_g   = (const float*)d_in[14];
    const float* m1a_beta= (const float*)d_in[15];
    const float* m1b_w   = (const float*)d_in[16];
    const float* m1b_b   = (const float*)d_in[17];
    const float* m1b_g   = (const float*)d_in[18];
    const float* m1b_beta= (const float*)d_in[19];
    const float* t1_w    = (const float*)d_in[20];
    const float* t1_b    = (const float*)d_in[21];
    const float* t2_w    = (const float*)d_in[22];
    const float* t2_b    = (const float*)d_in[23];
    const float* pos2_w  = (const float*)d_in[24];
    const float* pos2_b  = (const float*)d_in[25];
    const float* gn2_g   = (const float*)d_in[26];
    const float* gn2_b   = (const float*)d_in[27];
    const float* m2a_w   = (const float*)d_in[28];
    const float* m2a_b   = (const float*)d_in[29];
    const float* m2a_g   = (const float*)d_in[30];
    const float* m2a_beta= (const float*)d_in[31];
    float* out = (float*)d_out;

    float *f1T,*f2T,*g1T,*g2T,*fn1T,*fn2T,*bufA,*bufB,*stats,*dir12,*dir21;
    unsigned *Wh,*Wl;
    int *idx12,*idx21;
    cudaGetSymbolAddress((void**)&f1T,  g_f1T);
    cudaGetSymbolAddress((void**)&f2T,  g_f2T);
    cudaGetSymbolAddress((void**)&g1T,  g_g1T);
    cudaGetSymbolAddress((void**)&g2T,  g_g2T);
    cudaGetSymbolAddress((void**)&fn1T, g_fn1T);
    cudaGetSymbolAddress((void**)&fn2T, g_fn2T);
    cudaGetSymbolAddress((void**)&idx12,g_idx12);
    cudaGetSymbolAddress((void**)&idx21,g_idx21);
    cudaGetSymbolAddress((void**)&dir12,g_dir12);
    cudaGetSymbolAddress((void**)&dir21,g_dir21);
    cudaGetSymbolAddress((void**)&bufA, g_bufA);
    cudaGetSymbolAddress((void**)&bufB, g_bufB);
    cudaGetSymbolAddress((void**)&stats,g_stats);
    cudaGetSymbolAddress((void**)&Wh,   g_Wh);
    cudaGetSymbolAddress((void**)&Wl,   g_Wl);

    k_conv1d_in<<<dim3(NN/32, BB, 4), 128>>>(feat1, feat2, t11_w, t11_b, t22_w, t22_b, stats);
    k_knn<<<dim3(NN/32, BB, 2), 128>>>(pc1, pc2);

    // ---- cross1 + cross2 merged; tail blocks pack weights ----
    k_gather<<<dim3(NN/8 + 1, BB, 2), 128>>>(idx12, dir12, f1T, f2T,
                                             idx21, dir21, g1T, g2T,
                                             pos1_w, pos1_b, bufA, stats+0*STW,
                                             m1a_w, m1b_w, m2a_w);
    k_gemm<<<POS/128, 256>>>(bufA, Wh+0*64*128, Wl+0*64*128, m1a_b,
                             stats+0*STW, gn1_g, gn1_b, bufB, stats+1*STW);
    k_gemm<<<POS/128, 256>>>(bufB, Wh+1*64*128, Wl+1*64*128, m1b_b,
                             stats+1*STW, m1a_g, m1a_beta, bufA, stats+2*STW);
    k_poolconv<<<dim3(NN/32, BB, 2), 128>>>(bufA, stats+2*STW, m1b_g, m1b_beta,
                                            t1_w, t1_b, t2_w, t2_b,
                                            out, fn1T, fn2T);

    // ---- cross 3 ----
    k_gather<<<dim3(NN/8, BB, 1), 128>>>(idx12, dir12, fn1T, fn2T,
                                         idx12, dir12, fn1T, fn2T,
                                         pos2_w, pos2_b, bufA, stats+3*STW,
                                         m1a_w, m1b_w, m2a_w);
    k_gemm<<<PP/128, 256>>>(bufA, Wh+2*64*128, Wl+2*64*128, m2a_b,
                            stats+3*STW, gn2_g, gn2_b, bufB, stats+4*STW);
    k_pool<<<dim3(NN/8, BB, 1), 128>>>(bufB, stats+4*STW, m2a_g, m2a_beta,
                                       out + 2*BB*CC*NN);
}

// round 13
// speedup vs baseline: 1.1192x; 1.1192x over previous
#include <cuda_runtime.h>
#include <cuda_bf16.h>

#define BB 2
#define NN 4096
#define CC 128
#define CIN 64
#define KK 16
#define GG 8
#define PPB (NN*KK)       // 65536 positions per batch
#define PP (BB*PPB)       // 131072 positions per cross
#define POS (2*PP)        // merged cross1+cross2 position axis
#define EPSF 1e-5f
#define CNTF 1048576.0f   // 16 * 4096 * 16 elements per (cross,b,g)
#define NPITCH 72         // smem pair-row pitch (uint32) for 64-col tiles
#define STW (2*BB*GG*2)   // stats floats per stage (2 crosses x B x G x 2)

// ---------------- scratch (device globals; no allocs allowed) ----------------
__device__ float g_f1T[BB*NN*CC];
__device__ float g_f2T[BB*NN*CC];
__device__ float g_g1T[BB*NN*CC];
__device__ float g_g2T[BB*NN*CC];
__device__ float g_fn1T[BB*NN*CC];
__device__ float g_fn2T[BB*NN*CC];
__device__ int   g_idx12[BB*NN*KK];
__device__ int   g_idx21[BB*NN*KK];
__device__ float g_dir12[BB*NN*KK*3];
__device__ float g_dir21[BB*NN*KK*3];
__device__ float g_bufA[CC*POS];     // channel-major [c][cross*PP + p]
__device__ float g_bufB[CC*POS];
__device__ float g_stats[5*STW];     // per-stage (sum, sumsq)
__device__ unsigned g_Wh[3*64*128];  // packed bf16-hi pairs: [mat][kpair][orow]
__device__ unsigned g_Wl[3*64*128];  // packed bf16-lo pairs

// ---------------- helpers ----------------------------------------------------
__device__ __forceinline__ void bf16split(float v, unsigned short &h, unsigned short &l){
    __nv_bfloat16 hb = __float2bfloat16_rn(v);
    float hf = __bfloat162float(hb);
    __nv_bfloat16 lb = __float2bfloat16_rn(v - hf);
    h = *(unsigned short*)&hb;
    l = *(unsigned short*)&lb;
}
__device__ __forceinline__ unsigned pack2(unsigned short lo, unsigned short hi){
    return (unsigned)lo | ((unsigned)hi << 16);
}
__device__ __forceinline__ void mma16(float* d, const unsigned* a, unsigned b0, unsigned b1){
    asm("mma.sync.aligned.m16n8k16.row.col.f32.bf16.bf16.f32 "
        "{%0,%1,%2,%3},{%4,%5,%6,%7},{%8,%9},{%0,%1,%2,%3};"
        : "+f"(d[0]),"+f"(d[1]),"+f"(d[2]),"+f"(d[3])
        : "r"(a[0]),"r"(a[1]),"r"(a[2]),"r"(a[3]), "r"(b0),"r"(b1));
}

// -------- input 1x1 convs (+ stats zeroing folded into block 0) --------------
__global__ void k_conv1d_in(const float* __restrict__ feat1, const float* __restrict__ feat2,
                            const float* __restrict__ t11_w, const float* __restrict__ t11_b,
                            const float* __restrict__ t22_w, const float* __restrict__ t22_b,
                            float* __restrict__ stats) {
    if (blockIdx.x==0 && blockIdx.y==0 && blockIdx.z==0){
        for (int l=threadIdx.x; l<5*STW; l+=128) stats[l] = 0.f;
    }
    int job = blockIdx.z;
    int b = blockIdx.y;
    int n0 = blockIdx.x * 32;
    const float* x    = (job==0||job==3) ? feat1 : feat2;
    const float* w    = (job==0||job==2) ? t11_w : t22_w;
    const float* bias = (job==0||job==2) ? t11_b : t22_b;
    float* outp = (job==0) ? g_f1T : (job==1) ? g_f2T : (job==2) ? g_g1T : g_g2T;

    __shared__ float xs[CIN*33];
    int t = threadIdx.x;   // 128
    for (int l=t; l<CIN*32; l+=128) {
        int c=l>>5, j=l&31;
        xs[c*33+j] = x[(b*CIN+c)*NN + n0+j];
    }
    __syncthreads();
    int o = t;
    float wr[CIN];
#pragma unroll
    for (int c=0;c<CIN;c++) wr[c] = w[o*CIN+c];
    float bv = bias[o];
    for (int j=0;j<32;j++){
        float acc = bv;
#pragma unroll
        for (int c=0;c<CIN;c++) acc += wr[c]*xs[c*33+j];
        outp[(b*NN+n0+j)*CC + o] = acc;
    }
}

// ------- KNN (k=16): warp-granular 4-way candidate split + smem merge --------
__global__ void __launch_bounds__(128) k_knn(const float* __restrict__ pc1, const float* __restrict__ pc2) {
    int dir = blockIdx.z;
    const float* pq   = (dir==0) ? pc1 : pc2;
    const float* pcnd = (dir==0) ? pc2 : pc1;
    int*   idxo = (dir==0) ? g_idx12 : g_idx21;
    float* diro = (dir==0) ? g_dir12 : g_dir21;
    int b = blockIdx.y;
    int t = threadIdx.x;
    int q  = t >> 5;        // warp = candidate quarter
    int qi = t & 31;        // query within block (same across warps)
    int n = blockIdx.x*32 + qi;

    float qx = pq[(b*3+0)*NN+n], qy = pq[(b*3+1)*NN+n], qz = pq[(b*3+2)*NN+n];
    float s1 = qx*qx + qy*qy + qz*qz;

    float bd[KK]; int bi[KK];
#pragma unroll
    for (int k=0;k<KK;k++){ bd[k]=1e30f; bi[k]=0; }
    float worst = 1e30f;

    __shared__ float4 sc[1024];
    __shared__ float md[3*32*17];
    __shared__ int   mi[3*32*17];

    for (int r=0; r<4; r++) {
        __syncthreads();
        for (int i=t; i<1024; i+=128) {
            int hs = i >> 8;
            int m = hs*1024 + r*256 + (i & 255);
            float x = pcnd[(b*3+0)*NN+m];
            float y = pcnd[(b*3+1)*NN+m];
            float z = pcnd[(b*3+2)*NN+m];
            sc[i] = make_float4(x,y,z, x*x+y*y+z*z);
        }
        __syncthreads();
        int mbase = q*1024 + r*256;
        const float4* base = &sc[q*256];
#pragma unroll 4
        for (int i=0;i<256;i++) {
            float4 c = base[i];            // warp-broadcast read
            float d = s1 + c.w - 2.f*(qx*c.x + qy*c.y + qz*c.z);
            if (d < worst) {
                int miv = mbase + i;
                float nb[KK]; int ni[KK];
                bool c0 = bd[0] <= d;
                nb[0] = c0 ? bd[0] : d;
                ni[0] = c0 ? bi[0] : miv;
#pragma unroll
                for (int j=1;j<KK;j++){
                    bool cj  = bd[j]   <= d;
                    bool cjm = bd[j-1] <= d;
                    nb[j] = cj ? bd[j] : (cjm ? d : bd[j-1]);
                    ni[j] = cj ? bi[j] : (cjm ? miv : bi[j-1]);
                }
#pragma unroll
                for (int j=0;j<KK;j++){ bd[j]=nb[j]; bi[j]=ni[j]; }
                worst = bd[KK-1];
            }
        }
    }
    __syncthreads();
    if (q > 0){
#pragma unroll
        for (int k=0;k<KK;k++){
            md[((q-1)*32+qi)*17+k] = bd[k];
            mi[((q-1)*32+qi)*17+k] = bi[k];
        }
    }
    __syncthreads();
    if (q == 0){
        for (int s=0;s<3;s++){
#pragma unroll
            for (int k=0;k<KK;k++){
                float d = md[(s*32+qi)*17+k];
                if (d < worst){
                    int miv = mi[(s*32+qi)*17+k];
                    float nb[KK]; int ni[KK];
                    bool c0 = bd[0] <= d;
                    nb[0] = c0 ? bd[0] : d;
                    ni[0] = c0 ? bi[0] : miv;
#pragma unroll
                    for (int j=1;j<KK;j++){
                        bool cj  = bd[j]   <= d;
                        bool cjm = bd[j-1] <= d;
                        nb[j] = cj ? bd[j] : (cjm ? d : bd[j-1]);
                        ni[j] = cj ? bi[j] : (cjm ? miv : bi[j-1]);
                    }
#pragma unroll
                    for (int j=0;j<KK;j++){ bd[j]=nb[j]; bi[j]=ni[j]; }
                    worst = bd[KK-1];
                }
            }
        }
#pragma unroll
        for (int k=0;k<KK;k++){
            int m = bi[k];
            idxo[(b*NN+n)*KK+k] = m;
            float dx = pcnd[(b*3+0)*NN+m] - qx;
            float dy = pcnd[(b*3+1)*NN+m] - qy;
            float dz = pcnd[(b*3+2)*NN+m] - qz;
            diro[((b*NN+n)*KK+k)*3+0] = dx;
            diro[((b*NN+n)*KK+k)*3+1] = dy;
            diro[((b*NN+n)*KK+k)*3+2] = dz;
        }
    }
}

// -------- gather prologue (merged crosses; tail blocks pack weights) ---------
__global__ void k_gather(const int* __restrict__ idxA, const float* __restrict__ dirA,
                         const float* __restrict__ p1A, const float* __restrict__ p2A,
                         const int* __restrict__ idxB, const float* __restrict__ dirB,
                         const float* __restrict__ p1B, const float* __restrict__ p2B,
                         const float* __restrict__ pos_w, const float* __restrict__ pos_b,
                         float* __restrict__ X, float* __restrict__ stats,
                         const float* __restrict__ m1a, const float* __restrict__ m1b,
                         const float* __restrict__ m2a) {
    if (blockIdx.x >= NN/8){
        int j = blockIdx.z*BB + blockIdx.y;
        if (j < 3){
            const float* src = (j==0) ? m1a : (j==1) ? m1b : m2a;
            unsigned* dh = g_Wh + j*64*128;
            unsigned* dl = g_Wl + j*64*128;
            for (int l=threadIdx.x; l<64*128; l+=128){
                int kp = l >> 7, m = l & 127;
                unsigned short h0,l0,h1,l1;
                bf16split(src[m*CC + 2*kp],     h0, l0);
                bf16split(src[m*CC + 2*kp + 1], h1, l1);
                dh[l] = pack2(h0, h1);
                dl[l] = pack2(l0, l1);
            }
        }
        return;
    }
    int cross = blockIdx.z;
    const int*   idx  = cross ? idxB : idxA;
    const float* dirv = cross ? dirB : dirA;
    const float* p1T  = cross ? p1B : p1A;
    const float* p2T  = cross ? p2B : p2A;
    int b = blockIdx.y, n0 = blockIdx.x*8, c = threadIdx.x;
    float pw0 = pos_w[c*3+0], pw1 = pos_w[c*3+1], pw2 = pos_w[c*3+2], pb = pos_b[c];
    __shared__ float sh[CC*33];
    float sum=0.f, sq=0.f;
    int pbase = cross*PP + b*PPB + n0*KK;
    int lane = threadIdx.x & 31, r0 = threadIdx.x >> 5;

    for (int half=0; half<4; half++){
        for (int nn=0; nn<2; nn++){
            int n = n0 + half*2 + nn;
            float p1v = p1T[(b*NN+n)*CC + c];
            const int* ip = &idx[(b*NN+n)*KK];
            const float* dp0 = &dirv[(b*NN+n)*KK*3];
            for (int k=0;k<KK;k++){
                int m = ip[k];
                float pf = pw0*dp0[k*3+0] + pw1*dp0[k*3+1] + pw2*dp0[k*3+2] + pb;
                float v = p2T[(b*NN+m)*CC + c] + p1v + pf;
                sum += v; sq += v*v;
                sh[c*33 + nn*KK + k] = v;
            }
        }
        __syncthreads();
        int po = pbase + half*32;
        for (int r=r0; r<CC; r+=4)
            X[(size_t)r*POS + po + lane] = sh[r*33 + lane];
        __syncthreads();
    }
#pragma unroll
    for (int off=8; off; off>>=1){
        sum += __shfl_down_sync(0xffffffffu, sum, off, 16);
        sq  += __shfl_down_sync(0xffffffffu, sq,  off, 16);
    }
    if ((threadIdx.x & 15)==0){
        int g = c >> 4;
        int slot = (cross*BB + b)*GG + g;
        atomicAdd(&stats[slot*2+0], sum);
        atomicAdd(&stats[slot*2+1], sq);
    }
}

// ---- fused GN+LReLU(load) -> bf16 3-term mma GEMM (128M x 64N blocks) -------
// Small tiles -> ~70 regs, ~6KB smem -> 3 blocks/SM, 24 warps resident.
__global__ void __launch_bounds__(256, 3) k_gemm(const float* __restrict__ X,
        const unsigned* __restrict__ Whp, const unsigned* __restrict__ Wlp,
        const float* __restrict__ bias,
        const float* __restrict__ statsIn, const float* __restrict__ gamma,
        const float* __restrict__ beta, float* __restrict__ Y,
        float* __restrict__ statsOut) {
    __shared__ unsigned Xh[8*NPITCH], Xl[8*NPITCH];
    __shared__ float2 ssS[CC];

    int t = threadIdx.x;
    int pbase = blockIdx.x * 64;
    int cross = pbase >> 17;
    int b = (pbase >> 16) & 1;
    int slotB = (cross*BB + b)*GG;
    if (t < CC) {
        int g = t >> 4;
        float s = statsIn[(slotB+g)*2+0], q = statsIn[(slotB+g)*2+1];
        float mu = s / CNTF;
        float var = q / CNTF - mu*mu;
        float rstd = rsqrtf(var + EPSF);
        float scale = rstd * gamma[t];
        ssS[t] = make_float2(scale, beta[t] - mu*scale);
    }
    __syncthreads();

    int lane = t & 31, w = t >> 5;
    int gid = lane >> 2, tig = lane & 3;
    int om = (w & 3) * 32;      // warp M base (4 groups cover all 128 channels)
    int pn = (w >> 2) * 32;     // warp N base (2 groups cover the 64 positions)

    float acc[2][4][4];
#pragma unroll
    for (int i=0;i<2;i++)
#pragma unroll
        for (int j=0;j<4;j++)
#pragma unroll
            for (int r=0;r<4;r++) acc[i][j][r]=0.f;

    for (int ch=0; ch<8; ch++) {
        int kc8 = ch*8;
        __syncthreads();
        // stage 8 k-pairs x 64 cols, bf16 hi/lo split (2 slots per thread)
#pragma unroll
        for (int i=0;i<2;i++){
            int l = t + i*256;          // 0..511
            int k2 = l>>6, col = l&63;
            int kk = (kc8 + k2)*2;
            float2 s0 = ssS[kk], s1 = ssS[kk+1];
            float x0 = X[(size_t)kk*POS + pbase + col]*s0.x + s0.y;
            float x1 = X[(size_t)(kk+1)*POS + pbase + col]*s1.x + s1.y;
            x0 = (x0>=0.f) ? x0 : 0.1f*x0;
            x1 = (x1>=0.f) ? x1 : 0.1f*x1;
            unsigned short h0,l0,h1,l1;
            bf16split(x0, h0, l0);
            bf16split(x1, h1, l1);
            Xh[k2*NPITCH+col] = pack2(h0, h1);
            Xl[k2*NPITCH+col] = pack2(l0, l1);
        }
        __syncthreads();

        unsigned ah[2][4], al[2][4];
#pragma unroll
        for (int tm=0;tm<2;tm++){
            int mrow = om + tm*16 + gid;
            const unsigned* wh0 = &Whp[(kc8+tig)*128];
            const unsigned* wh4 = &Whp[(kc8+tig+4)*128];
            const unsigned* wl0 = &Wlp[(kc8+tig)*128];
            const unsigned* wl4 = &Wlp[(kc8+tig+4)*128];
            ah[tm][0] = __ldg(wh0 + mrow);
            ah[tm][1] = __ldg(wh0 + mrow + 8);
            ah[tm][2] = __ldg(wh4 + mrow);
            ah[tm][3] = __ldg(wh4 + mrow + 8);
            al[tm][0] = __ldg(wl0 + mrow);
            al[tm][1] = __ldg(wl0 + mrow + 8);
            al[tm][2] = __ldg(wl4 + mrow);
            al[tm][3] = __ldg(wl4 + mrow + 8);
        }
#pragma unroll
        for (int tn=0;tn<4;tn++){
            int p = pn + tn*8 + gid;
            unsigned bh0 = Xh[tig*NPITCH + p];
            unsigned bh1 = Xh[(tig+4)*NPITCH + p];
            unsigned bl0 = Xl[tig*NPITCH + p];
            unsigned bl1 = Xl[(tig+4)*NPITCH + p];
            mma16(acc[0][tn], ah[0], bh0, bh1);
            mma16(acc[1][tn], ah[1], bh0, bh1);
            mma16(acc[0][tn], al[0], bh0, bh1);
            mma16(acc[1][tn], al[1], bh0, bh1);
            mma16(acc[0][tn], ah[0], bl0, bl1);
            mma16(acc[1][tn], ah[1], bl0, bl1);
        }
    }

    // epilogue: bias, stores, GN stats
    float ssum[2] = {0.f, 0.f}, sq[2] = {0.f, 0.f};
#pragma unroll
    for (int tm=0;tm<2;tm++){
        int row0 = om + tm*16 + gid;
        float bv0 = bias[row0], bv1 = bias[row0+8];
#pragma unroll
        for (int tn=0;tn<4;tn++){
            float y0 = acc[tm][tn][0] + bv0;
            float y1 = acc[tm][tn][1] + bv0;
            float y2 = acc[tm][tn][2] + bv1;
            float y3 = acc[tm][tn][3] + bv1;
            ssum[tm] += (y0+y1)+(y2+y3);
            sq[tm]   += (y0*y0+y1*y1)+(y2*y2+y3*y3);
            int col = pbase + pn + tn*8 + tig*2;
            *(float2*)&Y[(size_t)row0*POS + col]     = make_float2(y0,y1);
            *(float2*)&Y[(size_t)(row0+8)*POS + col] = make_float2(y2,y3);
        }
    }
#pragma unroll
    for (int off=16; off; off>>=1){
        ssum[0] += __shfl_down_sync(0xffffffffu, ssum[0], off);
        sq[0]   += __shfl_down_sync(0xffffffffu, sq[0],   off);
        ssum[1] += __shfl_down_sync(0xffffffffu, ssum[1], off);
        sq[1]   += __shfl_down_sync(0xffffffffu, sq[1],   off);
    }
    if (lane == 0){
        int gb = (w & 3)*2;
        atomicAdd(&statsOut[(slotB+gb)*2+0],   ssum[0]);
        atomicAdd(&statsOut[(slotB+gb)*2+1],   sq[0]);
        atomicAdd(&statsOut[(slotB+gb+1)*2+0], ssum[1]);
        atomicAdd(&statsOut[(slotB+gb+1)*2+1], sq[1]);
    }
}

// ---- fused GN+LReLU + max-pool + trailing 1x1 conv (crosses 1/2) ------------
__global__ void __launch_bounds__(128) k_poolconv(const float* __restrict__ Y,
                          const float* __restrict__ statsIn,
                          const float* __restrict__ gamma, const float* __restrict__ beta,
                          const float* __restrict__ t1_w, const float* __restrict__ t1_b,
                          const float* __restrict__ t2_w, const float* __restrict__ t2_b,
                          float* __restrict__ outBase, float* __restrict__ fn1T,
                          float* __restrict__ fn2T) {
    int cross = blockIdx.z;
    int b = blockIdx.y;
    int t = threadIdx.x;
    int n0 = blockIdx.x*32;
    int p0 = cross*PP + b*PPB + n0*KK;      // 512 positions
    const float* w    = cross ? t2_w : t1_w;
    const float* bias = cross ? t2_b : t1_b;
    float* outCM = outBase + (size_t)cross*BB*CC*NN;
    float* fnT   = cross ? fn2T : fn1T;
    int slotB = (cross*BB + b)*GG;

    __shared__ float2 ssS[CC];
    __shared__ float xs[CC*36];
    if (t < CC){
        int g = t >> 4;
        float s = statsIn[(slotB+g)*2+0], q = statsIn[(slotB+g)*2+1];
        float mu = s / CNTF;
        float var = q / CNTF - mu*mu;
        float rstd = rsqrtf(var + EPSF);
        float scale = rstd * gamma[t];
        ssS[t] = make_float2(scale, beta[t] - mu*scale);
    }
    __syncthreads();

    int kk = t & 15;
#pragma unroll 2
    for (int c=0;c<CC;c++){
        float2 ss = ssS[c];
        const float* yrow = &Y[(size_t)c*POS + p0];
#pragma unroll
        for (int j=0;j<4;j++){
            float v = yrow[t + j*128]*ss.x + ss.y;
            v = (v>=0.f) ? v : 0.1f*v;
#pragma unroll
            for (int off=8; off; off>>=1)
                v = fmaxf(v, __shfl_xor_sync(0xffffffffu, v, off, 16));
            if (kk == 0) xs[c*36 + ((t + j*128)>>4)] = v;
        }
    }
    __syncthreads();

    int o = t;
    float acc[32];
    float bv = bias[o];
#pragma unroll
    for (int j=0;j<32;j++) acc[j]=bv;
    for (int cc=0; cc<4; cc++){
        float wr[32];
#pragma unroll
        for (int c2=0;c2<32;c2++) wr[c2] = w[o*CC + cc*32 + c2];
#pragma unroll
        for (int c2=0;c2<32;c2++){
            const float* xrow = &xs[(cc*32+c2)*36];
            float wv = wr[c2];
#pragma unroll
            for (int j4=0;j4<8;j4++){
                float4 xv = *(const float4*)&xrow[j4*4];
                acc[j4*4+0]+=wv*xv.x; acc[j4*4+1]+=wv*xv.y;
                acc[j4*4+2]+=wv*xv.z; acc[j4*4+3]+=wv*xv.w;
            }
        }
    }
#pragma unroll
    for (int j=0;j<32;j++) fnT[(b*NN+n0+j)*CC + o] = acc[j];
    __syncthreads();
#pragma unroll
    for (int j=0;j<32;j++) xs[o*36+j] = acc[j];
    __syncthreads();
    int lane = t & 31, r0 = t >> 5;
    for (int r=r0; r<CC; r+=4)
        outCM[(b*CC+r)*NN + n0 + lane] = xs[r*36+lane];
}

// ------- GN+LReLU apply + max-pool over K (cross3 epilogue) ------------------
__global__ void __launch_bounds__(128) k_pool(const float* __restrict__ Y,
                       const float* __restrict__ statsIn,
                       const float* __restrict__ gamma, const float* __restrict__ beta,
                       float* __restrict__ outCM) {
    int b = blockIdx.y;
    int t = threadIdx.x;
    int p0 = b*PPB + blockIdx.x*128;
    int nb = blockIdx.x*8 + (t >> 4);
    int kk = t & 15;
    int slotB = b*GG;
    __shared__ float2 ssS[CC];
    if (t < CC){
        int g = t >> 4;
        float s = statsIn[(slotB+g)*2+0], q = statsIn[(slotB+g)*2+1];
        float mu = s / CNTF;
        float var = q / CNTF - mu*mu;
        float rstd = rsqrtf(var + EPSF);
        float scale = rstd * gamma[t];
        ssS[t] = make_float2(scale, beta[t] - mu*scale);
    }
    __syncthreads();
#pragma unroll 4
    for (int c=0;c<CC;c++){
        float2 ss = ssS[c];
        float v = Y[(size_t)c*POS + p0 + t]*ss.x + ss.y;
        v = (v>=0.f) ? v : 0.1f*v;
#pragma unroll
        for (int off=8; off; off>>=1)
            v = fmaxf(v, __shfl_xor_sync(0xffffffffu, v, off, 16));
        if (kk == 0)
            outCM[(b*CC+c)*NN + nb] = v;
    }
}

// ---------------- host orchestration ----------------------------------------
extern "C" void kernel_launch(void* const* d_in, const int* in_sizes, int n_in,
                              void* d_out, int out_size) {
    const float* pc1     = (const float*)d_in[0];
    const float* pc2     = (const float*)d_in[1];
    const float* feat1   = (const float*)d_in[2];
    const float* feat2   = (const float*)d_in[3];
    const float* t11_w   = (const float*)d_in[4];
    const float* t11_b   = (const float*)d_in[5];
    const float* t22_w   = (const float*)d_in[6];
    const float* t22_b   = (const float*)d_in[7];
    const float* pos1_w  = (const float*)d_in[8];
    const float* pos1_b  = (const float*)d_in[9];
    const float* gn1_g   = (const float*)d_in[10];
    const float* gn1_b   = (const float*)d_in[11];
    const float* m1a_w   = (const float*)d_in[12];
    const float* m1a_b   = (const float*)d_in[13];
    const float* m1a_g   = (const float*)d_in[14];
    const float* m1a_beta= (const float*)d_in[15];
    const float* m1b_w   = (const float*)d_in[16];
    const float* m1b_b   = (const float*)d_in[17];
    const float* m1b_g   = (const float*)d_in[18];
    const float* m1b_beta= (const float*)d_in[19];
    const float* t1_w    = (const float*)d_in[20];
    const float* t1_b    = (const float*)d_in[21];
    const float* t2_w    = (const float*)d_in[22];
    const float* t2_b    = (const float*)d_in[23];
    const float* pos2_w  = (const float*)d_in[24];
    const float* pos2_b  = (const float*)d_in[25];
    const float* gn2_g   = (const float*)d_in[26];
    const float* gn2_b   = (const float*)d_in[27];
    const float* m2a_w   = (const float*)d_in[28];
    const float* m2a_b   = (const float*)d_in[29];
    const float* m2a_g   = (const float*)d_in[30];
    const float* m2a_beta= (const float*)d_in[31];
    float* out = (float*)d_out;

    float *f1T,*f2T,*g1T,*g2T,*fn1T,*fn2T,*bufA,*bufB,*stats,*dir12,*dir21;
    unsigned *Wh,*Wl;
    int *idx12,*idx21;
    cudaGetSymbolAddress((void**)&f1T,  g_f1T);
    cudaGetSymbolAddress((void**)&f2T,  g_f2T);
    cudaGetSymbolAddress((void**)&g1T,  g_g1T);
    cudaGetSymbolAddress((void**)&g2T,  g_g2T);
    cudaGetSymbolAddress((void**)&fn1T, g_fn1T);
    cudaGetSymbolAddress((void**)&fn2T, g_fn2T);
    cudaGetSymbolAddress((void**)&idx12,g_idx12);
    cudaGetSymbolAddress((void**)&idx21,g_idx21);
    cudaGetSymbolAddress((void**)&dir12,g_dir12);
    cudaGetSymbolAddress((void**)&dir21,g_dir21);
    cudaGetSymbolAddress((void**)&bufA, g_bufA);
    cudaGetSymbolAddress((void**)&bufB, g_bufB);
    cudaGetSymbolAddress((void**)&stats,g_stats);
    cudaGetSymbolAddress((void**)&Wh,   g_Wh);
    cudaGetSymbolAddress((void**)&Wl,   g_Wl);

    k_conv1d_in<<<dim3(NN/32, BB, 4), 128>>>(feat1, feat2, t11_w, t11_b, t22_w, t22_b, stats);
    k_knn<<<dim3(NN/32, BB, 2), 128>>>(pc1, pc2);

    // ---- cross1 + cross2 merged; tail blocks pack weights ----
    k_gather<<<dim3(NN/8 + 1, BB, 2), 128>>>(idx12, dir12, f1T, f2T,
                                             idx21, dir21, g1T, g2T,
                                             pos1_w, pos1_b, bufA, stats+0*STW,
                                             m1a_w, m1b_w, m2a_w);
    k_gemm<<<POS/64, 256>>>(bufA, Wh+0*64*128, Wl+0*64*128, m1a_b,
                            stats+0*STW, gn1_g, gn1_b, bufB, stats+1*STW);
    k_gemm<<<POS/64, 256>>>(bufB, Wh+1*64*128, Wl+1*64*128, m1b_b,
                            stats+1*STW, m1a_g, m1a_beta, bufA, stats+2*STW);
    k_poolconv<<<dim3(NN/32, BB, 2), 128>>>(bufA, stats+2*STW, m1b_g, m1b_beta,
                                            t1_w, t1_b, t2_w, t2_b,
                                            out, fn1T, fn2T);

    // ---- cross 3 ----
    k_gather<<<dim3(NN/8, BB, 1), 128>>>(idx12, dir12, fn1T, fn2T,
                                         idx12, dir12, fn1T, fn2T,
                                         pos2_w, pos2_b, bufA, stats+3*STW,
                                         m1a_w, m1b_w, m2a_w);
    k_gemm<<<PP/64, 256>>>(bufA, Wh+2*64*128, Wl+2*64*128, m2a_b,
                           stats+3*STW, gn2_g, gn2_b, bufB, stats+4*STW);
    k_pool<<<dim3(NN/8, BB, 1), 128>>>(bufB, stats+4*STW, m2a_g, m2a_beta,
                                       out + 2*BB*CC*NN);
}

// round 14
// speedup vs baseline: 1.2259x; 1.0954x over previous
#include <cuda_runtime.h>
#include <cuda_bf16.h>

#define BB 2
#define NN 4096
#define CC 128
#define CIN 64
#define KK 16
#define GG 8
#define PPB (NN*KK)       // 65536 positions per batch
#define PP (BB*PPB)       // 131072 positions per cross
#define POS (2*PP)        // merged cross1+cross2 position axis
#define EPSF 1e-5f
#define CNTF 1048576.0f   // 16 * 4096 * 16 elements per (cross,b,g)
#define UPITCH 136        // smem pair-row pitch (uint32); 4*34 -> 16B-aligned rows
#define STW (2*BB*GG*2)   // stats floats per stage (2 crosses x B x G x 2)

// ---------------- scratch (device globals; no allocs allowed) ----------------
__device__ float g_f1T[BB*NN*CC];
__device__ float g_f2T[BB*NN*CC];
__device__ float g_g1T[BB*NN*CC];
__device__ float g_g2T[BB*NN*CC];
__device__ float g_fn1T[BB*NN*CC];
__device__ float g_fn2T[BB*NN*CC];
__device__ int   g_idx12[BB*NN*KK];
__device__ int   g_idx21[BB*NN*KK];
__device__ float g_dir12[BB*NN*KK*3];
__device__ float g_dir21[BB*NN*KK*3];
__device__ float g_bufA[CC*POS];     // channel-major [c][cross*PP + p]
__device__ float g_bufB[CC*POS];
__device__ float g_stats[5*STW];     // per-stage (sum, sumsq)
__device__ unsigned g_Wh[3*64*128];  // packed bf16-hi pairs: [mat][kpair][orow]
__device__ unsigned g_Wl[3*64*128];  // packed bf16-lo pairs

// ---------------- helpers ----------------------------------------------------
__device__ __forceinline__ void bf16split(float v, unsigned short &h, unsigned short &l){
    __nv_bfloat16 hb = __float2bfloat16_rn(v);
    float hf = __bfloat162float(hb);
    __nv_bfloat16 lb = __float2bfloat16_rn(v - hf);
    h = *(unsigned short*)&hb;
    l = *(unsigned short*)&lb;
}
__device__ __forceinline__ unsigned pack2(unsigned short lo, unsigned short hi){
    return (unsigned)lo | ((unsigned)hi << 16);
}
__device__ __forceinline__ void mma16(float* d, const unsigned* a, unsigned b0, unsigned b1){
    asm("mma.sync.aligned.m16n8k16.row.col.f32.bf16.bf16.f32 "
        "{%0,%1,%2,%3},{%4,%5,%6,%7},{%8,%9},{%0,%1,%2,%3};"
        : "+f"(d[0]),"+f"(d[1]),"+f"(d[2]),"+f"(d[3])
        : "r"(a[0]),"r"(a[1]),"r"(a[2]),"r"(a[3]), "r"(b0),"r"(b1));
}

// -------- input 1x1 convs (+ stats zeroing folded into block 0) --------------
__global__ void k_conv1d_in(const float* __restrict__ feat1, const float* __restrict__ feat2,
                            const float* __restrict__ t11_w, const float* __restrict__ t11_b,
                            const float* __restrict__ t22_w, const float* __restrict__ t22_b,
                            float* __restrict__ stats) {
    if (blockIdx.x==0 && blockIdx.y==0 && blockIdx.z==0){
        for (int l=threadIdx.x; l<5*STW; l+=128) stats[l] = 0.f;
    }
    int job = blockIdx.z;
    int b = blockIdx.y;
    int n0 = blockIdx.x * 32;
    const float* x    = (job==0||job==3) ? feat1 : feat2;
    const float* w    = (job==0||job==2) ? t11_w : t22_w;
    const float* bias = (job==0||job==2) ? t11_b : t22_b;
    float* outp = (job==0) ? g_f1T : (job==1) ? g_f2T : (job==2) ? g_g1T : g_g2T;

    __shared__ float xs[CIN*33];
    int t = threadIdx.x;   // 128
    for (int l=t; l<CIN*32; l+=128) {
        int c=l>>5, j=l&31;
        xs[c*33+j] = x[(b*CIN+c)*NN + n0+j];
    }
    __syncthreads();
    int o = t;
    float wr[CIN];
#pragma unroll
    for (int c=0;c<CIN;c++) wr[c] = w[o*CIN+c];
    float bv = bias[o];
    for (int j=0;j<32;j++){
        float acc = bv;
#pragma unroll
        for (int c=0;c<CIN;c++) acc += wr[c]*xs[c*33+j];
        outp[(b*NN+n0+j)*CC + o] = acc;
    }
}

// ------- KNN (k=16): warp-granular 4-way candidate split + smem merge --------
__global__ void __launch_bounds__(128) k_knn(const float* __restrict__ pc1, const float* __restrict__ pc2) {
    int dir = blockIdx.z;
    const float* pq   = (dir==0) ? pc1 : pc2;
    const float* pcnd = (dir==0) ? pc2 : pc1;
    int*   idxo = (dir==0) ? g_idx12 : g_idx21;
    float* diro = (dir==0) ? g_dir12 : g_dir21;
    int b = blockIdx.y;
    int t = threadIdx.x;
    int q  = t >> 5;        // warp = candidate quarter
    int qi = t & 31;        // query within block (same across warps)
    int n = blockIdx.x*32 + qi;

    float qx = pq[(b*3+0)*NN+n], qy = pq[(b*3+1)*NN+n], qz = pq[(b*3+2)*NN+n];
    float s1 = qx*qx + qy*qy + qz*qz;

    float bd[KK]; int bi[KK];
#pragma unroll
    for (int k=0;k<KK;k++){ bd[k]=1e30f; bi[k]=0; }
    float worst = 1e30f;

    __shared__ float4 sc[1024];
    __shared__ float md[3*32*17];
    __shared__ int   mi[3*32*17];

    for (int r=0; r<4; r++) {
        __syncthreads();
        for (int i=t; i<1024; i+=128) {
            int hs = i >> 8;
            int m = hs*1024 + r*256 + (i & 255);
            float x = pcnd[(b*3+0)*NN+m];
            float y = pcnd[(b*3+1)*NN+m];
            float z = pcnd[(b*3+2)*NN+m];
            sc[i] = make_float4(x,y,z, x*x+y*y+z*z);
        }
        __syncthreads();
        int mbase = q*1024 + r*256;
        const float4* base = &sc[q*256];
#pragma unroll 4
        for (int i=0;i<256;i++) {
            float4 c = base[i];            // warp-broadcast read
            float d = s1 + c.w - 2.f*(qx*c.x + qy*c.y + qz*c.z);
            if (d < worst) {
                int miv = mbase + i;
                float nb[KK]; int ni[KK];
                bool c0 = bd[0] <= d;
                nb[0] = c0 ? bd[0] : d;
                ni[0] = c0 ? bi[0] : miv;
#pragma unroll
                for (int j=1;j<KK;j++){
                    bool cj  = bd[j]   <= d;
                    bool cjm = bd[j-1] <= d;
                    nb[j] = cj ? bd[j] : (cjm ? d : bd[j-1]);
                    ni[j] = cj ? bi[j] : (cjm ? miv : bi[j-1]);
                }
#pragma unroll
                for (int j=0;j<KK;j++){ bd[j]=nb[j]; bi[j]=ni[j]; }
                worst = bd[KK-1];
            }
        }
    }
    __syncthreads();
    if (q > 0){
#pragma unroll
        for (int k=0;k<KK;k++){
            md[((q-1)*32+qi)*17+k] = bd[k];
            mi[((q-1)*32+qi)*17+k] = bi[k];
        }
    }
    __syncthreads();
    if (q == 0){
        for (int s=0;s<3;s++){
#pragma unroll
            for (int k=0;k<KK;k++){
                float d = md[(s*32+qi)*17+k];
                if (d < worst){
                    int miv = mi[(s*32+qi)*17+k];
                    float nb[KK]; int ni[KK];
                    bool c0 = bd[0] <= d;
                    nb[0] = c0 ? bd[0] : d;
                    ni[0] = c0 ? bi[0] : miv;
#pragma unroll
                    for (int j=1;j<KK;j++){
                        bool cj  = bd[j]   <= d;
                        bool cjm = bd[j-1] <= d;
                        nb[j] = cj ? bd[j] : (cjm ? d : bd[j-1]);
                        ni[j] = cj ? bi[j] : (cjm ? miv : bi[j-1]);
                    }
#pragma unroll
                    for (int j=0;j<KK;j++){ bd[j]=nb[j]; bi[j]=ni[j]; }
                    worst = bd[KK-1];
                }
            }
        }
#pragma unroll
        for (int k=0;k<KK;k++){
            int m = bi[k];
            idxo[(b*NN+n)*KK+k] = m;
            float dx = pcnd[(b*3+0)*NN+m] - qx;
            float dy = pcnd[(b*3+1)*NN+m] - qy;
            float dz = pcnd[(b*3+2)*NN+m] - qz;
            diro[((b*NN+n)*KK+k)*3+0] = dx;
            diro[((b*NN+n)*KK+k)*3+1] = dy;
            diro[((b*NN+n)*KK+k)*3+2] = dz;
        }
    }
}

// -------- gather prologue (merged crosses; tail blocks pack weights) ---------
__global__ void k_gather(const int* __restrict__ idxA, const float* __restrict__ dirA,
                         const float* __restrict__ p1A, const float* __restrict__ p2A,
                         const int* __restrict__ idxB, const float* __restrict__ dirB,
                         const float* __restrict__ p1B, const float* __restrict__ p2B,
                         const float* __restrict__ pos_w, const float* __restrict__ pos_b,
                         float* __restrict__ X, float* __restrict__ stats,
                         const float* __restrict__ m1a, const float* __restrict__ m1b,
                         const float* __restrict__ m2a) {
    if (blockIdx.x >= NN/8){
        int j = blockIdx.z*BB + blockIdx.y;
        if (j < 3){
            const float* src = (j==0) ? m1a : (j==1) ? m1b : m2a;
            unsigned* dh = g_Wh + j*64*128;
            unsigned* dl = g_Wl + j*64*128;
            for (int l=threadIdx.x; l<64*128; l+=128){
                int kp = l >> 7, m = l & 127;
                unsigned short h0,l0,h1,l1;
                bf16split(src[m*CC + 2*kp],     h0, l0);
                bf16split(src[m*CC + 2*kp + 1], h1, l1);
                dh[l] = pack2(h0, h1);
                dl[l] = pack2(l0, l1);
            }
        }
        return;
    }
    int cross = blockIdx.z;
    const int*   idx  = cross ? idxB : idxA;
    const float* dirv = cross ? dirB : dirA;
    const float* p1T  = cross ? p1B : p1A;
    const float* p2T  = cross ? p2B : p2A;
    int b = blockIdx.y, n0 = blockIdx.x*8, c = threadIdx.x;
    float pw0 = pos_w[c*3+0], pw1 = pos_w[c*3+1], pw2 = pos_w[c*3+2], pb = pos_b[c];
    __shared__ float sh[CC*33];
    float sum=0.f, sq=0.f;
    int pbase = cross*PP + b*PPB + n0*KK;
    int lane = threadIdx.x & 31, r0 = threadIdx.x >> 5;

    for (int half=0; half<4; half++){
        for (int nn=0; nn<2; nn++){
            int n = n0 + half*2 + nn;
            float p1v = p1T[(b*NN+n)*CC + c];
            const int* ip = &idx[(b*NN+n)*KK];
            const float* dp0 = &dirv[(b*NN+n)*KK*3];
            for (int k=0;k<KK;k++){
                int m = ip[k];
                float pf = pw0*dp0[k*3+0] + pw1*dp0[k*3+1] + pw2*dp0[k*3+2] + pb;
                float v = p2T[(b*NN+m)*CC + c] + p1v + pf;
                sum += v; sq += v*v;
                sh[c*33 + nn*KK + k] = v;
            }
        }
        __syncthreads();
        int po = pbase + half*32;
        for (int r=r0; r<CC; r+=4)
            X[(size_t)r*POS + po + lane] = sh[r*33 + lane];
        __syncthreads();
    }
#pragma unroll
    for (int off=8; off; off>>=1){
        sum += __shfl_down_sync(0xffffffffu, sum, off, 16);
        sq  += __shfl_down_sync(0xffffffffu, sq,  off, 16);
    }
    if ((threadIdx.x & 15)==0){
        int g = c >> 4;
        int slot = (cross*BB + b)*GG + g;
        atomicAdd(&stats[slot*2+0], sum);
        atomicAdd(&stats[slot*2+1], sq);
    }
}

// ---- fused GN+LReLU(load) -> bf16 3-term mma GEMM (vectorized staging) ------
__global__ void __launch_bounds__(256) k_gemm(const float* __restrict__ X,
        const unsigned* __restrict__ Whp, const unsigned* __restrict__ Wlp,
        const float* __restrict__ bias,
        const float* __restrict__ statsIn, const float* __restrict__ gamma,
        const float* __restrict__ beta, float* __restrict__ Y,
        float* __restrict__ statsOut) {
    __shared__ unsigned Xh[8*UPITCH], Xl[8*UPITCH];
    __shared__ float2 ssS[CC];

    int t = threadIdx.x;
    int pbase = blockIdx.x * 128;
    int cross = pbase >> 17;
    int b = (pbase >> 16) & 1;
    int slotB = (cross*BB + b)*GG;
    if (t < CC) {
        int g = t >> 4;
        float s = statsIn[(slotB+g)*2+0], q = statsIn[(slotB+g)*2+1];
        float mu = s / CNTF;
        float var = q / CNTF - mu*mu;
        float rstd = rsqrtf(var + EPSF);
        float scale = rstd * gamma[t];
        ssS[t] = make_float2(scale, beta[t] - mu*scale);
    }
    __syncthreads();

    int lane = t & 31, w = t >> 5;
    int gid = lane >> 2, tig = lane & 3;
    int om = (w & 3) * 32;      // warp M (output-channel) base
    int pn = (w >> 2) * 64;     // warp N (position) base within the 128 tile

    // staging unit: one (k-pair, col4) per thread
    int sk2 = t >> 5;           // 0..7
    int scol = (t & 31) * 4;    // 0,4,...,124

    float acc[2][8][4];
#pragma unroll
    for (int i=0;i<2;i++)
#pragma unroll
        for (int j=0;j<8;j++)
#pragma unroll
            for (int r=0;r<4;r++) acc[i][j][r]=0.f;

    for (int ch=0; ch<8; ch++) {
        int kc8 = ch*8;
        __syncthreads();
        // vectorized stage: 2 LDG.128 + 8 splits + 2 STS.128 per thread
        {
            int kk = (kc8 + sk2)*2;
            float2 s0 = ssS[kk], s1 = ssS[kk+1];
            float4 xa = *(const float4*)&X[(size_t)kk*POS + pbase + scol];
            float4 xb = *(const float4*)&X[(size_t)(kk+1)*POS + pbase + scol];
            float a0 = xa.x*s0.x + s0.y, a1 = xa.y*s0.x + s0.y;
            float a2 = xa.z*s0.x + s0.y, a3 = xa.w*s0.x + s0.y;
            float b0 = xb.x*s1.x + s1.y, b1 = xb.y*s1.x + s1.y;
            float b2 = xb.z*s1.x + s1.y, b3 = xb.w*s1.x + s1.y;
            a0 = (a0>=0.f)?a0:0.1f*a0; a1 = (a1>=0.f)?a1:0.1f*a1;
            a2 = (a2>=0.f)?a2:0.1f*a2; a3 = (a3>=0.f)?a3:0.1f*a3;
            b0 = (b0>=0.f)?b0:0.1f*b0; b1 = (b1>=0.f)?b1:0.1f*b1;
            b2 = (b2>=0.f)?b2:0.1f*b2; b3 = (b3>=0.f)?b3:0.1f*b3;
            unsigned short ha0,la0,ha1,la1,ha2,la2,ha3,la3;
            unsigned short hb0,lb0,hb1,lb1,hb2,lb2,hb3,lb3;
            bf16split(a0,ha0,la0); bf16split(a1,ha1,la1);
            bf16split(a2,ha2,la2); bf16split(a3,ha3,la3);
            bf16split(b0,hb0,lb0); bf16split(b1,hb1,lb1);
            bf16split(b2,hb2,lb2); bf16split(b3,hb3,lb3);
            uint4 vh = make_uint4(pack2(ha0,hb0), pack2(ha1,hb1),
                                  pack2(ha2,hb2), pack2(ha3,hb3));
            uint4 vl = make_uint4(pack2(la0,lb0), pack2(la1,lb1),
                                  pack2(la2,lb2), pack2(la3,lb3));
            *(uint4*)&Xh[sk2*UPITCH + scol] = vh;
            *(uint4*)&Xl[sk2*UPITCH + scol] = vl;
        }
        __syncthreads();

        unsigned ah[2][4], al[2][4];
#pragma unroll
        for (int tm=0;tm<2;tm++){
            int mrow = om + tm*16 + gid;
            const unsigned* wh0 = &Whp[(kc8+tig)*128];
            const unsigned* wh4 = &Whp[(kc8+tig+4)*128];
            const unsigned* wl0 = &Wlp[(kc8+tig)*128];
            const unsigned* wl4 = &Wlp[(kc8+tig+4)*128];
            ah[tm][0] = __ldg(wh0 + mrow);
            ah[tm][1] = __ldg(wh0 + mrow + 8);
            ah[tm][2] = __ldg(wh4 + mrow);
            ah[tm][3] = __ldg(wh4 + mrow + 8);
            al[tm][0] = __ldg(wl0 + mrow);
            al[tm][1] = __ldg(wl0 + mrow + 8);
            al[tm][2] = __ldg(wl4 + mrow);
            al[tm][3] = __ldg(wl4 + mrow + 8);
        }
#pragma unroll
        for (int tn=0;tn<8;tn++){
            int p = pn + tn*8 + gid;
            unsigned bh0 = Xh[tig*UPITCH + p];
            unsigned bh1 = Xh[(tig+4)*UPITCH + p];
            unsigned bl0 = Xl[tig*UPITCH + p];
            unsigned bl1 = Xl[(tig+4)*UPITCH + p];
            mma16(acc[0][tn], ah[0], bh0, bh1);
            mma16(acc[1][tn], ah[1], bh0, bh1);
            mma16(acc[0][tn], al[0], bh0, bh1);
            mma16(acc[1][tn], al[1], bh0, bh1);
            mma16(acc[0][tn], ah[0], bl0, bl1);
            mma16(acc[1][tn], ah[1], bl0, bl1);
        }
    }

    // epilogue: bias, stores, GN stats
    float ssum[2] = {0.f, 0.f}, sq[2] = {0.f, 0.f};
#pragma unroll
    for (int tm=0;tm<2;tm++){
        int row0 = om + tm*16 + gid;
        float bv0 = bias[row0], bv1 = bias[row0+8];
#pragma unroll
        for (int tn=0;tn<8;tn++){
            float y0 = acc[tm][tn][0] + bv0;
            float y1 = acc[tm][tn][1] + bv0;
            float y2 = acc[tm][tn][2] + bv1;
            float y3 = acc[tm][tn][3] + bv1;
            ssum[tm] += (y0+y1)+(y2+y3);
            sq[tm]   += (y0*y0+y1*y1)+(y2*y2+y3*y3);
            int col = pbase + pn + tn*8 + tig*2;
            *(float2*)&Y[(size_t)row0*POS + col]     = make_float2(y0,y1);
            *(float2*)&Y[(size_t)(row0+8)*POS + col] = make_float2(y2,y3);
        }
    }
#pragma unroll
    for (int off=16; off; off>>=1){
        ssum[0] += __shfl_down_sync(0xffffffffu, ssum[0], off);
        sq[0]   += __shfl_down_sync(0xffffffffu, sq[0],   off);
        ssum[1] += __shfl_down_sync(0xffffffffu, ssum[1], off);
        sq[1]   += __shfl_down_sync(0xffffffffu, sq[1],   off);
    }
    if (lane == 0){
        int gb = (w & 3)*2;
        atomicAdd(&statsOut[(slotB+gb)*2+0],   ssum[0]);
        atomicAdd(&statsOut[(slotB+gb)*2+1],   sq[0]);
        atomicAdd(&statsOut[(slotB+gb+1)*2+0], ssum[1]);
        atomicAdd(&statsOut[(slotB+gb+1)*2+1], sq[1]);
    }
}

// ---- fused GN+LReLU + max-pool + trailing 1x1 conv (crosses 1/2) ------------
__global__ void __launch_bounds__(128) k_poolconv(const float* __restrict__ Y,
                          const float* __restrict__ statsIn,
                          const float* __restrict__ gamma, const float* __restrict__ beta,
                          const float* __restrict__ t1_w, const float* __restrict__ t1_b,
                          const float* __restrict__ t2_w, const float* __restrict__ t2_b,
                          float* __restrict__ outBase, float* __restrict__ fn1T,
                          float* __restrict__ fn2T) {
    int cross = blockIdx.z;
    int b = blockIdx.y;
    int t = threadIdx.x;
    int n0 = blockIdx.x*32;
    int p0 = cross*PP + b*PPB + n0*KK;      // 512 positions
    const float* w    = cross ? t2_w : t1_w;
    const float* bias = cross ? t2_b : t1_b;
    float* outCM = outBase + (size_t)cross*BB*CC*NN;
    float* fnT   = cross ? fn2T : fn1T;
    int slotB = (cross*BB + b)*GG;

    __shared__ float2 ssS[CC];
    __shared__ float xs[CC*36];
    if (t < CC){
        int g = t >> 4;
        float s = statsIn[(slotB+g)*2+0], q = statsIn[(slotB+g)*2+1];
        float mu = s / CNTF;
        float var = q / CNTF - mu*mu;
        float rstd = rsqrtf(var + EPSF);
        float scale = rstd * gamma[t];
        ssS[t] = make_float2(scale, beta[t] - mu*scale);
    }
    __syncthreads();

    int kk = t & 15;
#pragma unroll 2
    for (int c=0;c<CC;c++){
        float2 ss = ssS[c];
        const float* yrow = &Y[(size_t)c*POS + p0];
#pragma unroll
        for (int j=0;j<4;j++){
            float v = yrow[t + j*128]*ss.x + ss.y;
            v = (v>=0.f) ? v : 0.1f*v;
#pragma unroll
            for (int off=8; off; off>>=1)
                v = fmaxf(v, __shfl_xor_sync(0xffffffffu, v, off, 16));
            if (kk == 0) xs[c*36 + ((t + j*128)>>4)] = v;
        }
    }
    __syncthreads();

    int o = t;
    float acc[32];
    float bv = bias[o];
#pragma unroll
    for (int j=0;j<32;j++) acc[j]=bv;
    for (int cc=0; cc<4; cc++){
        float wr[32];
#pragma unroll
        for (int c2=0;c2<32;c2++) wr[c2] = w[o*CC + cc*32 + c2];
#pragma unroll
        for (int c2=0;c2<32;c2++){
            const float* xrow = &xs[(cc*32+c2)*36];
            float wv = wr[c2];
#pragma unroll
            for (int j4=0;j4<8;j4++){
                float4 xv = *(const float4*)&xrow[j4*4];
                acc[j4*4+0]+=wv*xv.x; acc[j4*4+1]+=wv*xv.y;
                acc[j4*4+2]+=wv*xv.z; acc[j4*4+3]+=wv*xv.w;
            }
        }
    }
#pragma unroll
    for (int j=0;j<32;j++) fnT[(b*NN+n0+j)*CC + o] = acc[j];
    __syncthreads();
#pragma unroll
    for (int j=0;j<32;j++) xs[o*36+j] = acc[j];
    __syncthreads();
    int lane = t & 31, r0 = t >> 5;
    for (int r=r0; r<CC; r+=4)
        outCM[(b*CC+r)*NN + n0 + lane] = xs[r*36+lane];
}

// ------- GN+LReLU apply + max-pool over K (cross3 epilogue) ------------------
__global__ void __launch_bounds__(128) k_pool(const float* __restrict__ Y,
                       const float* __restrict__ statsIn,
                       const float* __restrict__ gamma, const float* __restrict__ beta,
                       float* __restrict__ outCM) {
    int b = blockIdx.y;
    int t = threadIdx.x;
    int p0 = b*PPB + blockIdx.x*128;
    int nb = blockIdx.x*8 + (t >> 4);
    int kk = t & 15;
    int slotB = b*GG;
    __shared__ float2 ssS[CC];
    if (t < CC){
        int g = t >> 4;
        float s = statsIn[(slotB+g)*2+0], q = statsIn[(slotB+g)*2+1];
        float mu = s / CNTF;
        float var = q / CNTF - mu*mu;
        float rstd = rsqrtf(var + EPSF);
        float scale = rstd * gamma[t];
        ssS[t] = make_float2(scale, beta[t] - mu*scale);
    }
    __syncthreads();
#pragma unroll 4
    for (int c=0;c<CC;c++){
        float2 ss = ssS[c];
        float v = Y[(size_t)c*POS + p0 + t]*ss.x + ss.y;
        v = (v>=0.f) ? v : 0.1f*v;
#pragma unroll
        for (int off=8; off; off>>=1)
            v = fmaxf(v, __shfl_xor_sync(0xffffffffu, v, off, 16));
        if (kk == 0)
            outCM[(b*CC+c)*NN + nb] = v;
    }
}

// ---------------- host orchestration ----------------------------------------
extern "C" void kernel_launch(void* const* d_in, const int* in_sizes, int n_in,
                              void* d_out, int out_size) {
    const float* pc1     = (const float*)d_in[0];
    const float* pc2     = (const float*)d_in[1];
    const float* feat1   = (const float*)d_in[2];
    const float* feat2   = (const float*)d_in[3];
    const float* t11_w   = (const float*)d_in[4];
    const float* t11_b   = (const float*)d_in[5];
    const float* t22_w   = (const float*)d_in[6];
    const float* t22_b   = (const float*)d_in[7];
    const float* pos1_w  = (const float*)d_in[8];
    const float* pos1_b  = (const float*)d_in[9];
    const float* gn1_g   = (const float*)d_in[10];
    const float* gn1_b   = (const float*)d_in[11];
    const float* m1a_w   = (const float*)d_in[12];
    const float* m1a_b   = (const float*)d_in[13];
    const float* m1a_g   = (const float*)d_in[14];
    const float* m1a_beta= (const float*)d_in[15];
    const float* m1b_w   = (const float*)d_in[16];
    const float* m1b_b   = (const float*)d_in[17];
    const float* m1b_g   = (const float*)d_in[18];
    const float* m1b_beta= (const float*)d_in[19];
    const float* t1_w    = (const float*)d_in[20];
    const float* t1_b    = (const float*)d_in[21];
    const float* t2_w    = (const float*)d_in[22];
    const float* t2_b    = (const float*)d_in[23];
    const float* pos2_w  = (const float*)d_in[24];
    const float* pos2_b  = (const float*)d_in[25];
    const float* gn2_g   = (const float*)d_in[26];
    const float* gn2_b   = (const float*)d_in[27];
    const float* m2a_w   = (const float*)d_in[28];
    const float* m2a_b   = (const float*)d_in[29];
    const float* m2a_g   = (const float*)d_in[30];
    const float* m2a_beta= (const float*)d_in[31];
    float* out = (float*)d_out;

    float *f1T,*f2T,*g1T,*g2T,*fn1T,*fn2T,*bufA,*bufB,*stats,*dir12,*dir21;
    unsigned *Wh,*Wl;
    int *idx12,*idx21;
    cudaGetSymbolAddress((void**)&f1T,  g_f1T);
    cudaGetSymbolAddress((void**)&f2T,  g_f2T);
    cudaGetSymbolAddress((void**)&g1T,  g_g1T);
    cudaGetSymbolAddress((void**)&g2T,  g_g2T);
    cudaGetSymbolAddress((void**)&fn1T, g_fn1T);
    cudaGetSymbolAddress((void**)&fn2T, g_fn2T);
    cudaGetSymbolAddress((void**)&idx12,g_idx12);
    cudaGetSymbolAddress((void**)&idx21,g_idx21);
    cudaGetSymbolAddress((void**)&dir12,g_dir12);
    cudaGetSymbolAddress((void**)&dir21,g_dir21);
    cudaGetSymbolAddress((void**)&bufA, g_bufA);
    cudaGetSymbolAddress((void**)&bufB, g_bufB);
    cudaGetSymbolAddress((void**)&stats,g_stats);
    cudaGetSymbolAddress((void**)&Wh,   g_Wh);
    cudaGetSymbolAddress((void**)&Wl,   g_Wl);

    k_conv1d_in<<<dim3(NN/32, BB, 4), 128>>>(feat1, feat2, t11_w, t11_b, t22_w, t22_b, stats);
    k_knn<<<dim3(NN/32, BB, 2), 128>>>(pc1, pc2);

    // ---- cross1 + cross2 merged; tail blocks pack weights ----
    k_gather<<<dim3(NN/8 + 1, BB, 2), 128>>>(idx12, dir12, f1T, f2T,
                                             idx21, dir21, g1T, g2T,
                                             pos1_w, pos1_b, bufA, stats+0*STW,
                                             m1a_w, m1b_w, m2a_w);
    k_gemm<<<POS/128, 256>>>(bufA, Wh+0*64*128, Wl+0*64*128, m1a_b,
                             stats+0*STW, gn1_g, gn1_b, bufB, stats+1*STW);
    k_gemm<<<POS/128, 256>>>(bufB, Wh+1*64*128, Wl+1*64*128, m1b_b,
                             stats+1*STW, m1a_g, m1a_beta, bufA, stats+2*STW);
    k_poolconv<<<dim3(NN/32, BB, 2), 128>>>(bufA, stats+2*STW, m1b_g, m1b_beta,
                                            t1_w, t1_b, t2_w, t2_b,
                                            out, fn1T, fn2T);

    // ---- cross 3 ----
    k_gather<<<dim3(NN/8, BB, 1), 128>>>(idx12, dir12, fn1T, fn2T,
                                         idx12, dir12, fn1T, fn2T,
                                         pos2_w, pos2_b, bufA, stats+3*STW,
                                         m1a_w, m1b_w, m2a_w);
    k_gemm<<<PP/128, 256>>>(bufA, Wh+2*64*128, Wl+2*64*128, m2a_b,
                            stats+3*STW, gn2_g, gn2_b, bufB, stats+4*STW);
    k_pool<<<dim3(NN/8, BB, 1), 128>>>(bufB, stats+4*STW, m2a_g, m2a_beta,
                                       out + 2*BB*CC*NN);
}

// round 15
// speedup vs baseline: 1.4619x; 1.1925x over previous
#include <cuda_runtime.h>
#include <cuda_bf16.h>

#define BB 2
#define NN 4096
#define CC 128
#define CIN 64
#define KK 16
#define GG 8
#define PPB (NN*KK)       // 65536 positions per batch
#define PP (BB*PPB)       // 131072 positions per cross
#define POS (2*PP)        // merged cross1+cross2 position axis
#define EPSF 1e-5f
#define CNTF 1048576.0f   // 16 * 4096 * 16 elements per (cross,b,g)
#define UPITCH 136        // smem pair-row pitch (uint32); 4*34 -> 16B-aligned rows
#define STW (2*BB*GG*2)   // stats floats per stage (2 crosses x B x G x 2)

// ---------------- scratch (device globals; no allocs allowed) ----------------
__device__ float g_f1T[BB*NN*CC];
__device__ float g_f2T[BB*NN*CC];
__device__ float g_g1T[BB*NN*CC];
__device__ float g_g2T[BB*NN*CC];
__device__ float g_fn1T[BB*NN*CC];
__device__ float g_fn2T[BB*NN*CC];
__device__ int   g_idx12[BB*NN*KK];
__device__ int   g_idx21[BB*NN*KK];
__device__ float g_dir12[BB*NN*KK*4];   // float4-padded (dx,dy,dz,0)
__device__ float g_dir21[BB*NN*KK*4];
__device__ float g_bufA[CC*POS];     // channel-major [c][cross*PP + p]
__device__ float g_bufB[CC*POS];
__device__ float g_stats[5*STW];     // per-stage (sum, sumsq)
__device__ unsigned g_Wh[3*64*128];  // packed bf16-hi pairs: [mat][kpair][orow]
__device__ unsigned g_Wl[3*64*128];  // packed bf16-lo pairs

// ---------------- helpers ----------------------------------------------------
__device__ __forceinline__ void bf16split(float v, unsigned short &h, unsigned short &l){
    __nv_bfloat16 hb = __float2bfloat16_rn(v);
    float hf = __bfloat162float(hb);
    __nv_bfloat16 lb = __float2bfloat16_rn(v - hf);
    h = *(unsigned short*)&hb;
    l = *(unsigned short*)&lb;
}
__device__ __forceinline__ unsigned pack2(unsigned short lo, unsigned short hi){
    return (unsigned)lo | ((unsigned)hi << 16);
}
__device__ __forceinline__ void mma16(float* d, const unsigned* a, unsigned b0, unsigned b1){
    asm("mma.sync.aligned.m16n8k16.row.col.f32.bf16.bf16.f32 "
        "{%0,%1,%2,%3},{%4,%5,%6,%7},{%8,%9},{%0,%1,%2,%3};"
        : "+f"(d[0]),"+f"(d[1]),"+f"(d[2]),"+f"(d[3])
        : "r"(a[0]),"r"(a[1]),"r"(a[2]),"r"(a[3]), "r"(b0),"r"(b1));
}

// -------- input 1x1 convs (+ stats zeroing folded into block 0) --------------
__global__ void k_conv1d_in(const float* __restrict__ feat1, const float* __restrict__ feat2,
                            const float* __restrict__ t11_w, const float* __restrict__ t11_b,
                            const float* __restrict__ t22_w, const float* __restrict__ t22_b,
                            float* __restrict__ stats) {
    if (blockIdx.x==0 && blockIdx.y==0 && blockIdx.z==0){
        for (int l=threadIdx.x; l<5*STW; l+=128) stats[l] = 0.f;
    }
    int job = blockIdx.z;
    int b = blockIdx.y;
    int n0 = blockIdx.x * 32;
    const float* x    = (job==0||job==3) ? feat1 : feat2;
    const float* w    = (job==0||job==2) ? t11_w : t22_w;
    const float* bias = (job==0||job==2) ? t11_b : t22_b;
    float* outp = (job==0) ? g_f1T : (job==1) ? g_f2T : (job==2) ? g_g1T : g_g2T;

    __shared__ float xs[CIN*33];
    int t = threadIdx.x;   // 128
    for (int l=t; l<CIN*32; l+=128) {
        int c=l>>5, j=l&31;
        xs[c*33+j] = x[(b*CIN+c)*NN + n0+j];
    }
    __syncthreads();
    int o = t;
    float wr[CIN];
#pragma unroll
    for (int c=0;c<CIN;c++) wr[c] = w[o*CIN+c];
    float bv = bias[o];
    for (int j=0;j<32;j++){
        float acc = bv;
#pragma unroll
        for (int c=0;c<CIN;c++) acc += wr[c]*xs[c*33+j];
        outp[(b*NN+n0+j)*CC + o] = acc;
    }
}

// ------- KNN (k=16): warp-granular 4-way split + cheap in-place insert -------
__global__ void __launch_bounds__(128) k_knn(const float* __restrict__ pc1, const float* __restrict__ pc2) {
    int dir = blockIdx.z;
    const float* pq   = (dir==0) ? pc1 : pc2;
    const float* pcnd = (dir==0) ? pc2 : pc1;
    int*   idxo = (dir==0) ? g_idx12 : g_idx21;
    float* diro = (dir==0) ? g_dir12 : g_dir21;
    int b = blockIdx.y;
    int t = threadIdx.x;
    int q  = t >> 5;        // warp = candidate quarter
    int qi = t & 31;        // query within block (same across warps)
    int n = blockIdx.x*32 + qi;

    float qx = pq[(b*3+0)*NN+n], qy = pq[(b*3+1)*NN+n], qz = pq[(b*3+2)*NN+n];
    float s1 = qx*qx + qy*qy + qz*qz;

    float bd[KK]; int bi[KK];
#pragma unroll
    for (int k=0;k<KK;k++){ bd[k]=1e30f; bi[k]=0; }
    float worst = 1e30f;

    __shared__ float4 sc[1024];
    __shared__ float md[3*32*17];
    __shared__ int   mi[3*32*17];

    for (int r=0; r<4; r++) {
        __syncthreads();
        for (int i=t; i<1024; i+=128) {
            int hs = i >> 8;
            int m = hs*1024 + r*256 + (i & 255);
            float x = pcnd[(b*3+0)*NN+m];
            float y = pcnd[(b*3+1)*NN+m];
            float z = pcnd[(b*3+2)*NN+m];
            sc[i] = make_float4(x,y,z, x*x+y*y+z*z);
        }
        __syncthreads();
        int mbase = q*1024 + r*256;
        const float4* base = &sc[q*256];
#pragma unroll 4
        for (int i=0;i<256;i++) {
            float4 c = base[i];            // warp-broadcast read
            float d = s1 + c.w - 2.f*(qx*c.x + qy*c.y + qz*c.z);
            if (d < worst) {
                int miv = mbase + i;
                // in-place descending shift: j reads only j-1 (not yet touched)
                bool cj = bd[KK-1] > d;    // true here (d < worst = bd[15])
#pragma unroll
                for (int j=KK-1; j>=1; j--){
                    bool cjm = bd[j-1] > d;
                    float nv = cjm ? bd[j-1] : d;
                    int   niv = cjm ? bi[j-1] : miv;
                    bd[j] = cj ? nv  : bd[j];
                    bi[j] = cj ? niv : bi[j];
                    cj = cjm;
                }
                if (cj){ bd[0] = d; bi[0] = miv; }
                worst = bd[KK-1];
            }
        }
    }
    __syncthreads();
    if (q > 0){
#pragma unroll
        for (int k=0;k<KK;k++){
            md[((q-1)*32+qi)*17+k] = bd[k];
            mi[((q-1)*32+qi)*17+k] = bi[k];
        }
    }
    __syncthreads();
    if (q == 0){
        for (int s=0;s<3;s++){
#pragma unroll
            for (int k=0;k<KK;k++){
                float d = md[(s*32+qi)*17+k];
                if (d < worst){
                    int miv = mi[(s*32+qi)*17+k];
                    bool cj = bd[KK-1] > d;
#pragma unroll
                    for (int j=KK-1; j>=1; j--){
                        bool cjm = bd[j-1] > d;
                        float nv = cjm ? bd[j-1] : d;
                        int   niv = cjm ? bi[j-1] : miv;
                        bd[j] = cj ? nv  : bd[j];
                        bi[j] = cj ? niv : bi[j];
                        cj = cjm;
                    }
                    if (cj){ bd[0] = d; bi[0] = miv; }
                    worst = bd[KK-1];
                }
            }
        }
#pragma unroll
        for (int k=0;k<KK;k++){
            int m = bi[k];
            idxo[(b*NN+n)*KK+k] = m;
            float dx = pcnd[(b*3+0)*NN+m] - qx;
            float dy = pcnd[(b*3+1)*NN+m] - qy;
            float dz = pcnd[(b*3+2)*NN+m] - qz;
            *(float4*)&diro[((b*NN+n)*KK+k)*4] = make_float4(dx,dy,dz,0.f);
        }
    }
}

// -------- gather prologue (merged crosses; tail blocks pack weights) ---------
__global__ void k_gather(const int* __restrict__ idxA, const float* __restrict__ dirA,
                         const float* __restrict__ p1A, const float* __restrict__ p2A,
                         const int* __restrict__ idxB, const float* __restrict__ dirB,
                         const float* __restrict__ p1B, const float* __restrict__ p2B,
                         const float* __restrict__ pos_w, const float* __restrict__ pos_b,
                         float* __restrict__ X, float* __restrict__ stats,
                         const float* __restrict__ m1a, const float* __restrict__ m1b,
                         const float* __restrict__ m2a) {
    if (blockIdx.x >= NN/8){
        int j = blockIdx.z*BB + blockIdx.y;
        if (j < 3){
            const float* src = (j==0) ? m1a : (j==1) ? m1b : m2a;
            unsigned* dh = g_Wh + j*64*128;
            unsigned* dl = g_Wl + j*64*128;
            for (int l=threadIdx.x; l<64*128; l+=128){
                int kp = l >> 7, m = l & 127;
                unsigned short h0,l0,h1,l1;
                bf16split(src[m*CC + 2*kp],     h0, l0);
                bf16split(src[m*CC + 2*kp + 1], h1, l1);
                dh[l] = pack2(h0, h1);
                dl[l] = pack2(l0, l1);
            }
        }
        return;
    }
    int cross = blockIdx.z;
    const int*   idx  = cross ? idxB : idxA;
    const float* dirv = cross ? dirB : dirA;
    const float* p1T  = cross ? p1B : p1A;
    const float* p2T  = cross ? p2B : p2A;
    int b = blockIdx.y, n0 = blockIdx.x*8, c = threadIdx.x;
    float pw0 = pos_w[c*3+0], pw1 = pos_w[c*3+1], pw2 = pos_w[c*3+2], pb = pos_b[c];
    __shared__ float sh[CC*33];
    float sum=0.f, sq=0.f;
    int pbase = cross*PP + b*PPB + n0*KK;
    int lane = threadIdx.x & 31, r0 = threadIdx.x >> 5;

    for (int half=0; half<4; half++){
        for (int nn=0; nn<2; nn++){
            int n = n0 + half*2 + nn;
            float p1v = p1T[(b*NN+n)*CC + c];
            const int* ip = &idx[(b*NN+n)*KK];
            const float* dp0 = &dirv[(size_t)(b*NN+n)*KK*4];
            for (int k=0;k<KK;k++){
                int m = ip[k];
                float4 dv = *(const float4*)&dp0[k*4];
                float pf = pw0*dv.x + pw1*dv.y + pw2*dv.z + pb;
                float v = p2T[(b*NN+m)*CC + c] + p1v + pf;
                sum += v; sq += v*v;
                sh[c*33 + nn*KK + k] = v;
            }
        }
        __syncthreads();
        int po = pbase + half*32;
        for (int r=r0; r<CC; r+=4)
            X[(size_t)r*POS + po + lane] = sh[r*33 + lane];
        __syncthreads();
    }
#pragma unroll
    for (int off=8; off; off>>=1){
        sum += __shfl_down_sync(0xffffffffu, sum, off, 16);
        sq  += __shfl_down_sync(0xffffffffu, sq,  off, 16);
    }
    if ((threadIdx.x & 15)==0){
        int g = c >> 4;
        int slot = (cross*BB + b)*GG + g;
        atomicAdd(&stats[slot*2+0], sum);
        atomicAdd(&stats[slot*2+1], sq);
    }
}

// ---- fused GN+LReLU(load) -> bf16 3-term mma GEMM (vectorized staging) ------
__global__ void __launch_bounds__(256) k_gemm(const float* __restrict__ X,
        const unsigned* __restrict__ Whp, const unsigned* __restrict__ Wlp,
        const float* __restrict__ bias,
        const float* __restrict__ statsIn, const float* __restrict__ gamma,
        const float* __restrict__ beta, float* __restrict__ Y,
        float* __restrict__ statsOut) {
    __shared__ unsigned Xh[8*UPITCH], Xl[8*UPITCH];
    __shared__ float2 ssS[CC];

    int t = threadIdx.x;
    int pbase = blockIdx.x * 128;
    int cross = pbase >> 17;
    int b = (pbase >> 16) & 1;
    int slotB = (cross*BB + b)*GG;
    if (t < CC) {
        int g = t >> 4;
        float s = statsIn[(slotB+g)*2+0], q = statsIn[(slotB+g)*2+1];
        float mu = s / CNTF;
        float var = q / CNTF - mu*mu;
        float rstd = rsqrtf(var + EPSF);
        float scale = rstd * gamma[t];
        ssS[t] = make_float2(scale, beta[t] - mu*scale);
    }
    __syncthreads();

    int lane = t & 31, w = t >> 5;
    int gid = lane >> 2, tig = lane & 3;
    int om = (w & 3) * 32;      // warp M (output-channel) base
    int pn = (w >> 2) * 64;     // warp N (position) base within the 128 tile

    // staging unit: one (k-pair, col4) per thread
    int sk2 = t >> 5;           // 0..7
    int scol = (t & 31) * 4;    // 0,4,...,124

    float acc[2][8][4];
#pragma unroll
    for (int i=0;i<2;i++)
#pragma unroll
        for (int j=0;j<8;j++)
#pragma unroll
            for (int r=0;r<4;r++) acc[i][j][r]=0.f;

    for (int ch=0; ch<8; ch++) {
        int kc8 = ch*8;
        __syncthreads();
        // vectorized stage: 2 LDG.128 + 8 splits + 2 STS.128 per thread
        {
            int kk = (kc8 + sk2)*2;
            float2 s0 = ssS[kk], s1 = ssS[kk+1];
            float4 xa = *(const float4*)&X[(size_t)kk*POS + pbase + scol];
            float4 xb = *(const float4*)&X[(size_t)(kk+1)*POS + pbase + scol];
            float a0 = xa.x*s0.x + s0.y, a1 = xa.y*s0.x + s0.y;
            float a2 = xa.z*s0.x + s0.y, a3 = xa.w*s0.x + s0.y;
            float b0 = xb.x*s1.x + s1.y, b1 = xb.y*s1.x + s1.y;
            float b2 = xb.z*s1.x + s1.y, b3 = xb.w*s1.x + s1.y;
            a0 = (a0>=0.f)?a0:0.1f*a0; a1 = (a1>=0.f)?a1:0.1f*a1;
            a2 = (a2>=0.f)?a2:0.1f*a2; a3 = (a3>=0.f)?a3:0.1f*a3;
            b0 = (b0>=0.f)?b0:0.1f*b0; b1 = (b1>=0.f)?b1:0.1f*b1;
            b2 = (b2>=0.f)?b2:0.1f*b2; b3 = (b3>=0.f)?b3:0.1f*b3;
            unsigned short ha0,la0,ha1,la1,ha2,la2,ha3,la3;
            unsigned short hb0,lb0,hb1,lb1,hb2,lb2,hb3,lb3;
            bf16split(a0,ha0,la0); bf16split(a1,ha1,la1);
            bf16split(a2,ha2,la2); bf16split(a3,ha3,la3);
            bf16split(b0,hb0,lb0); bf16split(b1,hb1,lb1);
            bf16split(b2,hb2,lb2); bf16split(b3,hb3,lb3);
            uint4 vh = make_uint4(pack2(ha0,hb0), pack2(ha1,hb1),
                                  pack2(ha2,hb2), pack2(ha3,hb3));
            uint4 vl = make_uint4(pack2(la0,lb0), pack2(la1,lb1),
                                  pack2(la2,lb2), pack2(la3,lb3));
            *(uint4*)&Xh[sk2*UPITCH + scol] = vh;
            *(uint4*)&Xl[sk2*UPITCH + scol] = vl;
        }
        __syncthreads();

        unsigned ah[2][4], al[2][4];
#pragma unroll
        for (int tm=0;tm<2;tm++){
            int mrow = om + tm*16 + gid;
            const unsigned* wh0 = &Whp[(kc8+tig)*128];
            const unsigned* wh4 = &Whp[(kc8+tig+4)*128];
            const unsigned* wl0 = &Wlp[(kc8+tig)*128];
            const unsigned* wl4 = &Wlp[(kc8+tig+4)*128];
            ah[tm][0] = __ldg(wh0 + mrow);
            ah[tm][1] = __ldg(wh0 + mrow + 8);
            ah[tm][2] = __ldg(wh4 + mrow);
            ah[tm][3] = __ldg(wh4 + mrow + 8);
            al[tm][0] = __ldg(wl0 + mrow);
            al[tm][1] = __ldg(wl0 + mrow + 8);
            al[tm][2] = __ldg(wl4 + mrow);
            al[tm][3] = __ldg(wl4 + mrow + 8);
        }
#pragma unroll
        for (int tn=0;tn<8;tn++){
            int p = pn + tn*8 + gid;
            unsigned bh0 = Xh[tig*UPITCH + p];
            unsigned bh1 = Xh[(tig+4)*UPITCH + p];
            unsigned bl0 = Xl[tig*UPITCH + p];
            unsigned bl1 = Xl[(tig+4)*UPITCH + p];
            mma16(acc[0][tn], ah[0], bh0, bh1);
            mma16(acc[1][tn], ah[1], bh0, bh1);
            mma16(acc[0][tn], al[0], bh0, bh1);
            mma16(acc[1][tn], al[1], bh0, bh1);
            mma16(acc[0][tn], ah[0], bl0, bl1);
            mma16(acc[1][tn], ah[1], bl0, bl1);
        }
    }

    // epilogue: bias, stores, GN stats
    float ssum[2] = {0.f, 0.f}, sq[2] = {0.f, 0.f};
#pragma unroll
    for (int tm=0;tm<2;tm++){
        int row0 = om + tm*16 + gid;
        float bv0 = bias[row0], bv1 = bias[row0+8];
#pragma unroll
        for (int tn=0;tn<8;tn++){
            float y0 = acc[tm][tn][0] + bv0;
            float y1 = acc[tm][tn][1] + bv0;
            float y2 = acc[tm][tn][2] + bv1;
            float y3 = acc[tm][tn][3] + bv1;
            ssum[tm] += (y0+y1)+(y2+y3);
            sq[tm]   += (y0*y0+y1*y1)+(y2*y2+y3*y3);
            int col = pbase + pn + tn*8 + tig*2;
            *(float2*)&Y[(size_t)row0*POS + col]     = make_float2(y0,y1);
            *(float2*)&Y[(size_t)(row0+8)*POS + col] = make_float2(y2,y3);
        }
    }
#pragma unroll
    for (int off=16; off; off>>=1){
        ssum[0] += __shfl_down_sync(0xffffffffu, ssum[0], off);
        sq[0]   += __shfl_down_sync(0xffffffffu, sq[0],   off);
        ssum[1] += __shfl_down_sync(0xffffffffu, ssum[1], off);
        sq[1]   += __shfl_down_sync(0xffffffffu, sq[1],   off);
    }
    if (lane == 0){
        int gb = (w & 3)*2;
        atomicAdd(&statsOut[(slotB+gb)*2+0],   ssum[0]);
        atomicAdd(&statsOut[(slotB+gb)*2+1],   sq[0]);
        atomicAdd(&statsOut[(slotB+gb+1)*2+0], ssum[1]);
        atomicAdd(&statsOut[(slotB+gb+1)*2+1], sq[1]);
    }
}

// ---- fused GN+LReLU + max-pool + trailing 1x1 conv (crosses 1/2) ------------
__global__ void __launch_bounds__(128) k_poolconv(const float* __restrict__ Y,
                          const float* __restrict__ statsIn,
                          const float* __restrict__ gamma, const float* __restrict__ beta,
                          const float* __restrict__ t1_w, const float* __restrict__ t1_b,
                          const float* __restrict__ t2_w, const float* __restrict__ t2_b,
                          float* __restrict__ outBase, float* __restrict__ fn1T,
                          float* __restrict__ fn2T) {
    int cross = blockIdx.z;
    int b = blockIdx.y;
    int t = threadIdx.x;
    int n0 = blockIdx.x*32;
    int p0 = cross*PP + b*PPB + n0*KK;      // 512 positions
    const float* w    = cross ? t2_w : t1_w;
    const float* bias = cross ? t2_b : t1_b;
    float* outCM = outBase + (size_t)cross*BB*CC*NN;
    float* fnT   = cross ? fn2T : fn1T;
    int slotB = (cross*BB + b)*GG;

    __shared__ float2 ssS[CC];
    __shared__ float xs[CC*36];
    if (t < CC){
        int g = t >> 4;
        float s = statsIn[(slotB+g)*2+0], q = statsIn[(slotB+g)*2+1];
        float mu = s / CNTF;
        float var = q / CNTF - mu*mu;
        float rstd = rsqrtf(var + EPSF);
        float scale = rstd * gamma[t];
        ssS[t] = make_float2(scale, beta[t] - mu*scale);
    }
    __syncthreads();

    int kk = t & 15;
#pragma unroll 2
    for (int c=0;c<CC;c++){
        float2 ss = ssS[c];
        const float* yrow = &Y[(size_t)c*POS + p0];
#pragma unroll
        for (int j=0;j<4;j++){
            float v = yrow[t + j*128]*ss.x + ss.y;
            v = (v>=0.f) ? v : 0.1f*v;
#pragma unroll
            for (int off=8; off; off>>=1)
                v = fmaxf(v, __shfl_xor_sync(0xffffffffu, v, off, 16));
            if (kk == 0) xs[c*36 + ((t + j*128)>>4)] = v;
        }
    }
    __syncthreads();

    int o = t;
    float acc[32];
    float bv = bias[o];
#pragma unroll
    for (int j=0;j<32;j++) acc[j]=bv;
    for (int cc=0; cc<4; cc++){
        float wr[32];
#pragma unroll
        for (int c2=0;c2<32;c2++) wr[c2] = w[o*CC + cc*32 + c2];
#pragma unroll
        for (int c2=0;c2<32;c2++){
            const float* xrow = &xs[(cc*32+c2)*36];
            float wv = wr[c2];
#pragma unroll
            for (int j4=0;j4<8;j4++){
                float4 xv = *(const float4*)&xrow[j4*4];
                acc[j4*4+0]+=wv*xv.x; acc[j4*4+1]+=wv*xv.y;
                acc[j4*4+2]+=wv*xv.z; acc[j4*4+3]+=wv*xv.w;
            }
        }
    }
#pragma unroll
    for (int j=0;j<32;j++) fnT[(b*NN+n0+j)*CC + o] = acc[j];
    __syncthreads();
#pragma unroll
    for (int j=0;j<32;j++) xs[o*36+j] = acc[j];
    __syncthreads();
    int lane = t & 31, r0 = t >> 5;
    for (int r=r0; r<CC; r+=4)
        outCM[(b*CC+r)*NN + n0 + lane] = xs[r*36+lane];
}

// ------- GN+LReLU apply + max-pool over K (cross3 epilogue) ------------------
__global__ void __launch_bounds__(128) k_pool(const float* __restrict__ Y,
                       const float* __restrict__ statsIn,
                       const float* __restrict__ gamma, const float* __restrict__ beta,
                       float* __restrict__ outCM) {
    int b = blockIdx.y;
    int t = threadIdx.x;
    int p0 = b*PPB + blockIdx.x*128;
    int nb = blockIdx.x*8 + (t >> 4);
    int kk = t & 15;
    int slotB = b*GG;
    __shared__ float2 ssS[CC];
    if (t < CC){
        int g = t >> 4;
        float s = statsIn[(slotB+g)*2+0], q = statsIn[(slotB+g)*2+1];
        float mu = s / CNTF;
        float var = q / CNTF - mu*mu;
        float rstd = rsqrtf(var + EPSF);
        float scale = rstd * gamma[t];
        ssS[t] = make_float2(scale, beta[t] - mu*scale);
    }
    __syncthreads();
#pragma unroll 4
    for (int c=0;c<CC;c++){
        float2 ss = ssS[c];
        float v = Y[(size_t)c*POS + p0 + t]*ss.x + ss.y;
        v = (v>=0.f) ? v : 0.1f*v;
#pragma unroll
        for (int off=8; off; off>>=1)
            v = fmaxf(v, __shfl_xor_sync(0xffffffffu, v, off, 16));
        if (kk == 0)
            outCM[(b*CC+c)*NN + nb] = v;
    }
}

// ---------------- host orchestration ----------------------------------------
extern "C" void kernel_launch(void* const* d_in, const int* in_sizes, int n_in,
                              void* d_out, int out_size) {
    const float* pc1     = (const float*)d_in[0];
    const float* pc2     = (const float*)d_in[1];
    const float* feat1   = (const float*)d_in[2];
    const float* feat2   = (const float*)d_in[3];
    const float* t11_w   = (const float*)d_in[4];
    const float* t11_b   = (const float*)d_in[5];
    const float* t22_w   = (const float*)d_in[6];
    const float* t22_b   = (const float*)d_in[7];
    const float* pos1_w  = (const float*)d_in[8];
    const float* pos1_b  = (const float*)d_in[9];
    const float* gn1_g   = (const float*)d_in[10];
    const float* gn1_b   = (const float*)d_in[11];
    const float* m1a_w   = (const float*)d_in[12];
    const float* m1a_b   = (const float*)d_in[13];
    const float* m1a_g   = (const float*)d_in[14];
    const float* m1a_beta= (const float*)d_in[15];
    const float* m1b_w   = (const float*)d_in[16];
    const float* m1b_b   = (const float*)d_in[17];
    const float* m1b_g   = (const float*)d_in[18];
    const float* m1b_beta= (const float*)d_in[19];
    const float* t1_w    = (const float*)d_in[20];
    const float* t1_b    = (const float*)d_in[21];
    const float* t2_w    = (const float*)d_in[22];
    const float* t2_b    = (const float*)d_in[23];
    const float* pos2_w  = (const float*)d_in[24];
    const float* pos2_b  = (const float*)d_in[25];
    const float* gn2_g   = (const float*)d_in[26];
    const float* gn2_b   = (const float*)d_in[27];
    const float* m2a_w   = (const float*)d_in[28];
    const float* m2a_b   = (const float*)d_in[29];
    const float* m2a_g   = (const float*)d_in[30];
    const float* m2a_beta= (const float*)d_in[31];
    float* out = (float*)d_out;

    float *f1T,*f2T,*g1T,*g2T,*fn1T,*fn2T,*bufA,*bufB,*stats,*dir12,*dir21;
    unsigned *Wh,*Wl;
    int *idx12,*idx21;
    cudaGetSymbolAddress((void**)&f1T,  g_f1T);
    cudaGetSymbolAddress((void**)&f2T,  g_f2T);
    cudaGetSymbolAddress((void**)&g1T,  g_g1T);
    cudaGetSymbolAddress((void**)&g2T,  g_g2T);
    cudaGetSymbolAddress((void**)&fn1T, g_fn1T);
    cudaGetSymbolAddress((void**)&fn2T, g_fn2T);
    cudaGetSymbolAddress((void**)&idx12,g_idx12);
    cudaGetSymbolAddress((void**)&idx21,g_idx21);
    cudaGetSymbolAddress((void**)&dir12,g_dir12);
    cudaGetSymbolAddress((void**)&dir21,g_dir21);
    cudaGetSymbolAddress((void**)&bufA, g_bufA);
    cudaGetSymbolAddress((void**)&bufB, g_bufB);
    cudaGetSymbolAddress((void**)&stats,g_stats);
    cudaGetSymbolAddress((void**)&Wh,   g_Wh);
    cudaGetSymbolAddress((void**)&Wl,   g_Wl);

    k_conv1d_in<<<dim3(NN/32, BB, 4), 128>>>(feat1, feat2, t11_w, t11_b, t22_w, t22_b, stats);
    k_knn<<<dim3(NN/32, BB, 2), 128>>>(pc1, pc2);

    // ---- cross1 + cross2 merged; tail blocks pack weights ----
    k_gather<<<dim3(NN/8 + 1, BB, 2), 128>>>(idx12, dir12, f1T, f2T,
                                             idx21, dir21, g1T, g2T,
                                             pos1_w, pos1_b, bufA, stats+0*STW,
                                             m1a_w, m1b_w, m2a_w);
    k_gemm<<<POS/128, 256>>>(bufA, Wh+0*64*128, Wl+0*64*128, m1a_b,
                             stats+0*STW, gn1_g, gn1_b, bufB, stats+1*STW);
    k_gemm<<<POS/128, 256>>>(bufB, Wh+1*64*128, Wl+1*64*128, m1b_b,
                             stats+1*STW, m1a_g, m1a_beta, bufA, stats+2*STW);
    k_poolconv<<<dim3(NN/32, BB, 2), 128>>>(bufA, stats+2*STW, m1b_g, m1b_beta,
                                            t1_w, t1_b, t2_w, t2_b,
                                            out, fn1T, fn2T);

    // ---- cross 3 ----
    k_gather<<<dim3(NN/8, BB, 1), 128>>>(idx12, dir12, fn1T, fn2T,
                                         idx12, dir12, fn1T, fn2T,
                                         pos2_w, pos2_b, bufA, stats+3*STW,
                                         m1a_w, m1b_w, m2a_w);
    k_gemm<<<PP/128, 256>>>(bufA, Wh+2*64*128, Wl+2*64*128, m2a_b,
                            stats+3*STW, gn2_g, gn2_b, bufB, stats+4*STW);
    k_pool<<<dim3(NN/8, BB, 1), 128>>>(bufB, stats+4*STW, m2a_g, m2a_beta,
                                       out + 2*BB*CC*NN);
}

// round 16
// speedup vs baseline: 1.4739x; 1.0083x over previous
#include <cuda_runtime.h>
#include <cuda_bf16.h>

#define BB 2
#define NN 4096
#define CC 128
#define CIN 64
#define KK 16
#define GG 8
#define PPB (NN*KK)       // 65536 positions per batch
#define PP (BB*PPB)       // 131072 positions per cross
#define POS (2*PP)        // merged cross1+cross2 position axis
#define EPSF 1e-5f
#define CNTF 1048576.0f   // 16 * 4096 * 16 elements per (cross,b,g)
#define UPITCH 136        // smem pair-row pitch (uint32); 4*34 -> 16B-aligned rows
#define STW (2*BB*GG*2)   // stats floats per stage (2 crosses x B x G x 2)

// ---------------- scratch (device globals; no allocs allowed) ----------------
__device__ float g_f1T[BB*NN*CC];
__device__ float g_f2T[BB*NN*CC];
__device__ float g_g1T[BB*NN*CC];
__device__ float g_g2T[BB*NN*CC];
__device__ float g_fn1T[BB*NN*CC];
__device__ float g_fn2T[BB*NN*CC];
__device__ int   g_idx12[BB*NN*KK];
__device__ int   g_idx21[BB*NN*KK];
__device__ float g_dir12[BB*NN*KK*4];   // float4-padded (dx,dy,dz,0)
__device__ float g_dir21[BB*NN*KK*4];
__device__ float g_bufA[CC*POS];     // channel-major [c][cross*PP + p]
__device__ float g_bufB[CC*POS];
__device__ float g_stats[5*STW];     // per-stage (sum, sumsq)
__device__ unsigned g_Wh[3*64*128];  // packed bf16-hi pairs: [mat][kpair][orow]
__device__ unsigned g_Wl[3*64*128];  // packed bf16-lo pairs

// ---------------- helpers ----------------------------------------------------
__device__ __forceinline__ void bf16split(float v, unsigned short &h, unsigned short &l){
    __nv_bfloat16 hb = __float2bfloat16_rn(v);
    float hf = __bfloat162float(hb);
    __nv_bfloat16 lb = __float2bfloat16_rn(v - hf);
    h = *(unsigned short*)&hb;
    l = *(unsigned short*)&lb;
}
__device__ __forceinline__ unsigned pack2(unsigned short lo, unsigned short hi){
    return (unsigned)lo | ((unsigned)hi << 16);
}
__device__ __forceinline__ void mma16(float* d, const unsigned* a, unsigned b0, unsigned b1){
    asm("mma.sync.aligned.m16n8k16.row.col.f32.bf16.bf16.f32 "
        "{%0,%1,%2,%3},{%4,%5,%6,%7},{%8,%9},{%0,%1,%2,%3};"
        : "+f"(d[0]),"+f"(d[1]),"+f"(d[2]),"+f"(d[3])
        : "r"(a[0]),"r"(a[1]),"r"(a[2]),"r"(a[3]), "r"(b0),"r"(b1));
}

// -------- input 1x1 convs (+ stats zeroing folded into block 0) --------------
__global__ void k_conv1d_in(const float* __restrict__ feat1, const float* __restrict__ feat2,
                            const float* __restrict__ t11_w, const float* __restrict__ t11_b,
                            const float* __restrict__ t22_w, const float* __restrict__ t22_b,
                            float* __restrict__ stats) {
    if (blockIdx.x==0 && blockIdx.y==0 && blockIdx.z==0){
        for (int l=threadIdx.x; l<5*STW; l+=128) stats[l] = 0.f;
    }
    int job = blockIdx.z;
    int b = blockIdx.y;
    int n0 = blockIdx.x * 32;
    const float* x    = (job==0||job==3) ? feat1 : feat2;
    const float* w    = (job==0||job==2) ? t11_w : t22_w;
    const float* bias = (job==0||job==2) ? t11_b : t22_b;
    float* outp = (job==0) ? g_f1T : (job==1) ? g_f2T : (job==2) ? g_g1T : g_g2T;

    __shared__ float xs[CIN*33];
    int t = threadIdx.x;   // 128
    for (int l=t; l<CIN*32; l+=128) {
        int c=l>>5, j=l&31;
        xs[c*33+j] = x[(b*CIN+c)*NN + n0+j];
    }
    __syncthreads();
    int o = t;
    float wr[CIN];
#pragma unroll
    for (int c=0;c<CIN;c++) wr[c] = w[o*CIN+c];
    float bv = bias[o];
    for (int j=0;j<32;j++){
        float acc = bv;
#pragma unroll
        for (int c=0;c<CIN;c++) acc += wr[c]*xs[c*33+j];
        outp[(b*NN+n0+j)*CC + o] = acc;
    }
}

// ------- KNN (k=16): warp-granular 4-way split + cheap in-place insert -------
__global__ void __launch_bounds__(128) k_knn(const float* __restrict__ pc1, const float* __restrict__ pc2) {
    int dir = blockIdx.z;
    const float* pq   = (dir==0) ? pc1 : pc2;
    const float* pcnd = (dir==0) ? pc2 : pc1;
    int*   idxo = (dir==0) ? g_idx12 : g_idx21;
    float* diro = (dir==0) ? g_dir12 : g_dir21;
    int b = blockIdx.y;
    int t = threadIdx.x;
    int q  = t >> 5;        // warp = candidate quarter
    int qi = t & 31;        // query within block (same across warps)
    int n = blockIdx.x*32 + qi;

    float qx = pq[(b*3+0)*NN+n], qy = pq[(b*3+1)*NN+n], qz = pq[(b*3+2)*NN+n];
    float s1 = qx*qx + qy*qy + qz*qz;

    float bd[KK]; int bi[KK];
#pragma unroll
    for (int k=0;k<KK;k++){ bd[k]=1e30f; bi[k]=0; }
    float worst = 1e30f;

    __shared__ float4 sc[1024];
    __shared__ float md[3*32*17];
    __shared__ int   mi[3*32*17];

    for (int r=0; r<4; r++) {
        __syncthreads();
        for (int i=t; i<1024; i+=128) {
            int hs = i >> 8;
            int m = hs*1024 + r*256 + (i & 255);
            float x = pcnd[(b*3+0)*NN+m];
            float y = pcnd[(b*3+1)*NN+m];
            float z = pcnd[(b*3+2)*NN+m];
            sc[i] = make_float4(x,y,z, x*x+y*y+z*z);
        }
        __syncthreads();
        int mbase = q*1024 + r*256;
        const float4* base = &sc[q*256];
#pragma unroll 4
        for (int i=0;i<256;i++) {
            float4 c = base[i];            // warp-broadcast read
            float d = s1 + c.w - 2.f*(qx*c.x + qy*c.y + qz*c.z);
            if (d < worst) {
                int miv = mbase + i;
                bool cj = bd[KK-1] > d;
#pragma unroll
                for (int j=KK-1; j>=1; j--){
                    bool cjm = bd[j-1] > d;
                    float nv = cjm ? bd[j-1] : d;
                    int   niv = cjm ? bi[j-1] : miv;
                    bd[j] = cj ? nv  : bd[j];
                    bi[j] = cj ? niv : bi[j];
                    cj = cjm;
                }
                if (cj){ bd[0] = d; bi[0] = miv; }
                worst = bd[KK-1];
            }
        }
    }
    __syncthreads();
    if (q > 0){
#pragma unroll
        for (int k=0;k<KK;k++){
            md[((q-1)*32+qi)*17+k] = bd[k];
            mi[((q-1)*32+qi)*17+k] = bi[k];
        }
    }
    __syncthreads();
    if (q == 0){
        for (int s=0;s<3;s++){
#pragma unroll
            for (int k=0;k<KK;k++){
                float d = md[(s*32+qi)*17+k];
                if (d < worst){
                    int miv = mi[(s*32+qi)*17+k];
                    bool cj = bd[KK-1] > d;
#pragma unroll
                    for (int j=KK-1; j>=1; j--){
                        bool cjm = bd[j-1] > d;
                        float nv = cjm ? bd[j-1] : d;
                        int   niv = cjm ? bi[j-1] : miv;
                        bd[j] = cj ? nv  : bd[j];
                        bi[j] = cj ? niv : bi[j];
                        cj = cjm;
                    }
                    if (cj){ bd[0] = d; bi[0] = miv; }
                    worst = bd[KK-1];
                }
            }
        }
#pragma unroll
        for (int k=0;k<KK;k++){
            int m = bi[k];
            idxo[(b*NN+n)*KK+k] = m;
            float dx = pcnd[(b*3+0)*NN+m] - qx;
            float dy = pcnd[(b*3+1)*NN+m] - qy;
            float dz = pcnd[(b*3+2)*NN+m] - qz;
            *(float4*)&diro[((b*NN+n)*KK+k)*4] = make_float4(dx,dy,dz,0.f);
        }
    }
}

// ---- gather prologue (256 threads, k-split halves; tail blocks pack weights)
__global__ void __launch_bounds__(256) k_gather(
                         const int* __restrict__ idxA, const float* __restrict__ dirA,
                         const float* __restrict__ p1A, const float* __restrict__ p2A,
                         const int* __restrict__ idxB, const float* __restrict__ dirB,
                         const float* __restrict__ p1B, const float* __restrict__ p2B,
                         const float* __restrict__ pos_w, const float* __restrict__ pos_b,
                         float* __restrict__ X, float* __restrict__ stats,
                         const float* __restrict__ m1a, const float* __restrict__ m1b,
                         const float* __restrict__ m2a) {
    if (blockIdx.x >= NN/8){
        int j = blockIdx.z*BB + blockIdx.y;
        if (j < 3){
            const float* src = (j==0) ? m1a : (j==1) ? m1b : m2a;
            unsigned* dh = g_Wh + j*64*128;
            unsigned* dl = g_Wl + j*64*128;
            for (int l=threadIdx.x; l<64*128; l+=256){
                int kp = l >> 7, m = l & 127;
                unsigned short h0,l0,h1,l1;
                bf16split(src[m*CC + 2*kp],     h0, l0);
                bf16split(src[m*CC + 2*kp + 1], h1, l1);
                dh[l] = pack2(h0, h1);
                dl[l] = pack2(l0, l1);
            }
        }
        return;
    }
    int cross = blockIdx.z;
    const int*   idx  = cross ? idxB : idxA;
    const float* dirv = cross ? dirB : dirA;
    const float* p1T  = cross ? p1B : p1A;
    const float* p2T  = cross ? p2B : p2A;
    int b = blockIdx.y, n0 = blockIdx.x*8;
    int t = threadIdx.x;
    int c = t & 127;
    int kh = (t >> 7) * 8;     // k-half base: 0 or 8
    float pw0 = pos_w[c*3+0], pw1 = pos_w[c*3+1], pw2 = pos_w[c*3+2], pb = pos_b[c];
    __shared__ float sh[CC*33];
    float sum=0.f, sq=0.f;
    int pbase = cross*PP + b*PPB + n0*KK;
    int lane = t & 31, r0 = t >> 5;

    for (int half=0; half<4; half++){
        for (int nn=0; nn<2; nn++){
            int n = n0 + half*2 + nn;
            float p1v = p1T[(b*NN+n)*CC + c];
            const int* ip = &idx[(b*NN+n)*KK + kh];
            const float* dp0 = &dirv[((size_t)(b*NN+n)*KK + kh)*4];
#pragma unroll
            for (int k2=0;k2<8;k2++){
                int m = ip[k2];
                float4 dv = *(const float4*)&dp0[k2*4];
                float pf = pw0*dv.x + pw1*dv.y + pw2*dv.z + pb;
                float v = p2T[(b*NN+m)*CC + c] + p1v + pf;
                sum += v; sq += v*v;
                sh[c*33 + nn*KK + kh + k2] = v;
            }
        }
        __syncthreads();
        int po = pbase + half*32;
        for (int r=r0; r<CC; r+=8)
            X[(size_t)r*POS + po + lane] = sh[r*33 + lane];
        __syncthreads();
    }
#pragma unroll
    for (int off=8; off; off>>=1){
        sum += __shfl_down_sync(0xffffffffu, sum, off, 16);
        sq  += __shfl_down_sync(0xffffffffu, sq,  off, 16);
    }
    if ((t & 15)==0){
        int g = c >> 4;
        int slot = (cross*BB + b)*GG + g;
        atomicAdd(&stats[slot*2+0], sum);
        atomicAdd(&stats[slot*2+1], sq);
    }
}

// ---- fused GN+LReLU(load) -> bf16 3-term mma GEMM (vectorized staging) ------
__global__ void __launch_bounds__(256) k_gemm(const float* __restrict__ X,
        const unsigned* __restrict__ Whp, const unsigned* __restrict__ Wlp,
        const float* __restrict__ bias,
        const float* __restrict__ statsIn, const float* __restrict__ gamma,
        const float* __restrict__ beta, float* __restrict__ Y,
        float* __restrict__ statsOut) {
    __shared__ unsigned Xh[8*UPITCH], Xl[8*UPITCH];
    __shared__ float2 ssS[CC];

    int t = threadIdx.x;
    int pbase = blockIdx.x * 128;
    int cross = pbase >> 17;
    int b = (pbase >> 16) & 1;
    int slotB = (cross*BB + b)*GG;
    if (t < CC) {
        int g = t >> 4;
        float s = statsIn[(slotB+g)*2+0], q = statsIn[(slotB+g)*2+1];
        float mu = s / CNTF;
        float var = q / CNTF - mu*mu;
        float rstd = rsqrtf(var + EPSF);
        float scale = rstd * gamma[t];
        ssS[t] = make_float2(scale, beta[t] - mu*scale);
    }
    __syncthreads();

    int lane = t & 31, w = t >> 5;
    int gid = lane >> 2, tig = lane & 3;
    int om = (w & 3) * 32;      // warp M (output-channel) base
    int pn = (w >> 2) * 64;     // warp N (position) base within the 128 tile

    // staging unit: one (k-pair, col4) per thread
    int sk2 = t >> 5;           // 0..7
    int scol = (t & 31) * 4;    // 0,4,...,124

    float acc[2][8][4];
#pragma unroll
    for (int i=0;i<2;i++)
#pragma unroll
        for (int j=0;j<8;j++)
#pragma unroll
            for (int r=0;r<4;r++) acc[i][j][r]=0.f;

    for (int ch=0; ch<8; ch++) {
        int kc8 = ch*8;
        __syncthreads();
        // vectorized stage: 2 LDG.128 + 8 splits + 2 STS.128 per thread
        {
            int kk = (kc8 + sk2)*2;
            float2 s0 = ssS[kk], s1 = ssS[kk+1];
            float4 xa = *(const float4*)&X[(size_t)kk*POS + pbase + scol];
            float4 xb = *(const float4*)&X[(size_t)(kk+1)*POS + pbase + scol];
            float a0 = xa.x*s0.x + s0.y, a1 = xa.y*s0.x + s0.y;
            float a2 = xa.z*s0.x + s0.y, a3 = xa.w*s0.x + s0.y;
            float b0 = xb.x*s1.x + s1.y, b1 = xb.y*s1.x + s1.y;
            float b2 = xb.z*s1.x + s1.y, b3 = xb.w*s1.x + s1.y;
            a0 = (a0>=0.f)?a0:0.1f*a0; a1 = (a1>=0.f)?a1:0.1f*a1;
            a2 = (a2>=0.f)?a2:0.1f*a2; a3 = (a3>=0.f)?a3:0.1f*a3;
            b0 = (b0>=0.f)?b0:0.1f*b0; b1 = (b1>=0.f)?b1:0.1f*b1;
            b2 = (b2>=0.f)?b2:0.1f*b2; b3 = (b3>=0.f)?b3:0.1f*b3;
            unsigned short ha0,la0,ha1,la1,ha2,la2,ha3,la3;
            unsigned short hb0,lb0,hb1,lb1,hb2,lb2,hb3,lb3;
            bf16split(a0,ha0,la0); bf16split(a1,ha1,la1);
            bf16split(a2,ha2,la2); bf16split(a3,ha3,la3);
            bf16split(b0,hb0,lb0); bf16split(b1,hb1,lb1);
            bf16split(b2,hb2,lb2); bf16split(b3,hb3,lb3);
            uint4 vh = make_uint4(pack2(ha0,hb0), pack2(ha1,hb1),
                                  pack2(ha2,hb2), pack2(ha3,hb3));
            uint4 vl = make_uint4(pack2(la0,lb0), pack2(la1,lb1),
                                  pack2(la2,lb2), pack2(la3,lb3));
            *(uint4*)&Xh[sk2*UPITCH + scol] = vh;
            *(uint4*)&Xl[sk2*UPITCH + scol] = vl;
        }
        __syncthreads();

        unsigned ah[2][4], al[2][4];
#pragma unroll
        for (int tm=0;tm<2;tm++){
            int mrow = om + tm*16 + gid;
            const unsigned* wh0 = &Whp[(kc8+tig)*128];
            const unsigned* wh4 = &Whp[(kc8+tig+4)*128];
            const unsigned* wl0 = &Wlp[(kc8+tig)*128];
            const unsigned* wl4 = &Wlp[(kc8+tig+4)*128];
            ah[tm][0] = __ldg(wh0 + mrow);
            ah[tm][1] = __ldg(wh0 + mrow + 8);
            ah[tm][2] = __ldg(wh4 + mrow);
            ah[tm][3] = __ldg(wh4 + mrow + 8);
            al[tm][0] = __ldg(wl0 + mrow);
            al[tm][1] = __ldg(wl0 + mrow + 8);
            al[tm][2] = __ldg(wl4 + mrow);
            al[tm][3] = __ldg(wl4 + mrow + 8);
        }
#pragma unroll
        for (int tn=0;tn<8;tn++){
            int p = pn + tn*8 + gid;
            unsigned bh0 = Xh[tig*UPITCH + p];
            unsigned bh1 = Xh[(tig+4)*UPITCH + p];
            unsigned bl0 = Xl[tig*UPITCH + p];
            unsigned bl1 = Xl[(tig+4)*UPITCH + p];
            mma16(acc[0][tn], ah[0], bh0, bh1);
            mma16(acc[1][tn], ah[1], bh0, bh1);
            mma16(acc[0][tn], al[0], bh0, bh1);
            mma16(acc[1][tn], al[1], bh0, bh1);
            mma16(acc[0][tn], ah[0], bl0, bl1);
            mma16(acc[1][tn], ah[1], bl0, bl1);
        }
    }

    // epilogue: bias, stores, GN stats
    float ssum[2] = {0.f, 0.f}, sq[2] = {0.f, 0.f};
#pragma unroll
    for (int tm=0;tm<2;tm++){
        int row0 = om + tm*16 + gid;
        float bv0 = bias[row0], bv1 = bias[row0+8];
#pragma unroll
        for (int tn=0;tn<8;tn++){
            float y0 = acc[tm][tn][0] + bv0;
            float y1 = acc[tm][tn][1] + bv0;
            float y2 = acc[tm][tn][2] + bv1;
            float y3 = acc[tm][tn][3] + bv1;
            ssum[tm] += (y0+y1)+(y2+y3);
            sq[tm]   += (y0*y0+y1*y1)+(y2*y2+y3*y3);
            int col = pbase + pn + tn*8 + tig*2;
            *(float2*)&Y[(size_t)row0*POS + col]     = make_float2(y0,y1);
            *(float2*)&Y[(size_t)(row0+8)*POS + col] = make_float2(y2,y3);
        }
    }
#pragma unroll
    for (int off=16; off; off>>=1){
        ssum[0] += __shfl_down_sync(0xffffffffu, ssum[0], off);
        sq[0]   += __shfl_down_sync(0xffffffffu, sq[0],   off);
        ssum[1] += __shfl_down_sync(0xffffffffu, ssum[1], off);
        sq[1]   += __shfl_down_sync(0xffffffffu, sq[1],   off);
    }
    if (lane == 0){
        int gb = (w & 3)*2;
        atomicAdd(&statsOut[(slotB+gb)*2+0],   ssum[0]);
        atomicAdd(&statsOut[(slotB+gb)*2+1],   sq[0]);
        atomicAdd(&statsOut[(slotB+gb+1)*2+0], ssum[1]);
        atomicAdd(&statsOut[(slotB+gb+1)*2+1], sq[1]);
    }
}

// ---- fused GN+LReLU + max-pool + trailing 1x1 conv (crosses 1/2) ------------
__global__ void __launch_bounds__(128) k_poolconv(const float* __restrict__ Y,
                          const float* __restrict__ statsIn,
                          const float* __restrict__ gamma, const float* __restrict__ beta,
                          const float* __restrict__ t1_w, const float* __restrict__ t1_b,
                          const float* __restrict__ t2_w, const float* __restrict__ t2_b,
                          float* __restrict__ outBase, float* __restrict__ fn1T,
                          float* __restrict__ fn2T) {
    int cross = blockIdx.z;
    int b = blockIdx.y;
    int t = threadIdx.x;
    int n0 = blockIdx.x*32;
    int p0 = cross*PP + b*PPB + n0*KK;      // 512 positions
    const float* w    = cross ? t2_w : t1_w;
    const float* bias = cross ? t2_b : t1_b;
    float* outCM = outBase + (size_t)cross*BB*CC*NN;
    float* fnT   = cross ? fn2T : fn1T;
    int slotB = (cross*BB + b)*GG;

    __shared__ float2 ssS[CC];
    __shared__ float xs[CC*36];
    if (t < CC){
        int g = t >> 4;
        float s = statsIn[(slotB+g)*2+0], q = statsIn[(slotB+g)*2+1];
        float mu = s / CNTF;
        float var = q / CNTF - mu*mu;
        float rstd = rsqrtf(var + EPSF);
        float scale = rstd * gamma[t];
        ssS[t] = make_float2(scale, beta[t] - mu*scale);
    }
    __syncthreads();

    int kk = t & 15;
#pragma unroll 2
    for (int c=0;c<CC;c++){
        float2 ss = ssS[c];
        const float* yrow = &Y[(size_t)c*POS + p0];
#pragma unroll
        for (int j=0;j<4;j++){
            float v = yrow[t + j*128]*ss.x + ss.y;
            v = (v>=0.f) ? v : 0.1f*v;
#pragma unroll
            for (int off=8; off; off>>=1)
                v = fmaxf(v, __shfl_xor_sync(0xffffffffu, v, off, 16));
            if (kk == 0) xs[c*36 + ((t + j*128)>>4)] = v;
        }
    }
    __syncthreads();

    int o = t;
    float acc[32];
    float bv = bias[o];
#pragma unroll
    for (int j=0;j<32;j++) acc[j]=bv;
    for (int cc=0; cc<4; cc++){
        float wr[32];
#pragma unroll
        for (int c2=0;c2<32;c2++) wr[c2] = w[o*CC + cc*32 + c2];
#pragma unroll
        for (int c2=0;c2<32;c2++){
            const float* xrow = &xs[(cc*32+c2)*36];
            float wv = wr[c2];
#pragma unroll
            for (int j4=0;j4<8;j4++){
                float4 xv = *(const float4*)&xrow[j4*4];
                acc[j4*4+0]+=wv*xv.x; acc[j4*4+1]+=wv*xv.y;
                acc[j4*4+2]+=wv*xv.z; acc[j4*4+3]+=wv*xv.w;
            }
        }
    }
#pragma unroll
    for (int j=0;j<32;j++) fnT[(b*NN+n0+j)*CC + o] = acc[j];
    __syncthreads();
#pragma unroll
    for (int j=0;j<32;j++) xs[o*36+j] = acc[j];
    __syncthreads();
    int lane = t & 31, r0 = t >> 5;
    for (int r=r0; r<CC; r+=4)
        outCM[(b*CC+r)*NN + n0 + lane] = xs[r*36+lane];
}

// ------- GN+LReLU apply + max-pool over K (cross3 epilogue) ------------------
__global__ void __launch_bounds__(128) k_pool(const float* __restrict__ Y,
                       const float* __restrict__ statsIn,
                       const float* __restrict__ gamma, const float* __restrict__ beta,
                       float* __restrict__ outCM) {
    int b = blockIdx.y;
    int t = threadIdx.x;
    int p0 = b*PPB + blockIdx.x*128;
    int nb = blockIdx.x*8 + (t >> 4);
    int kk = t & 15;
    int slotB = b*GG;
    __shared__ float2 ssS[CC];
    if (t < CC){
        int g = t >> 4;
        float s = statsIn[(slotB+g)*2+0], q = statsIn[(slotB+g)*2+1];
        float mu = s / CNTF;
        float var = q / CNTF - mu*mu;
        float rstd = rsqrtf(var + EPSF);
        float scale = rstd * gamma[t];
        ssS[t] = make_float2(scale, beta[t] - mu*scale);
    }
    __syncthreads();
#pragma unroll 4
    for (int c=0;c<CC;c++){
        float2 ss = ssS[c];
        float v = Y[(size_t)c*POS + p0 + t]*ss.x + ss.y;
        v = (v>=0.f) ? v : 0.1f*v;
#pragma unroll
        for (int off=8; off; off>>=1)
            v = fmaxf(v, __shfl_xor_sync(0xffffffffu, v, off, 16));
        if (kk == 0)
            outCM[(b*CC+c)*NN + nb] = v;
    }
}

// ---------------- host orchestration ----------------------------------------
extern "C" void kernel_launch(void* const* d_in, const int* in_sizes, int n_in,
                              void* d_out, int out_size) {
    const float* pc1     = (const float*)d_in[0];
    const float* pc2     = (const float*)d_in[1];
    const float* feat1   = (const float*)d_in[2];
    const float* feat2   = (const float*)d_in[3];
    const float* t11_w   = (const float*)d_in[4];
    const float* t11_b   = (const float*)d_in[5];
    const float* t22_w   = (const float*)d_in[6];
    const float* t22_b   = (const float*)d_in[7];
    const float* pos1_w  = (const float*)d_in[8];
    const float* pos1_b  = (const float*)d_in[9];
    const float* gn1_g   = (const float*)d_in[10];
    const float* gn1_b   = (const float*)d_in[11];
    const float* m1a_w   = (const float*)d_in[12];
    const float* m1a_b   = (const float*)d_in[13];
    const float* m1a_g   = (const float*)d_in[14];
    const float* m1a_beta= (const float*)d_in[15];
    const float* m1b_w   = (const float*)d_in[16];
    const float* m1b_b   = (const float*)d_in[17];
    const float* m1b_g   = (const float*)d_in[18];
    const float* m1b_beta= (const float*)d_in[19];
    const float* t1_w    = (const float*)d_in[20];
    const float* t1_b    = (const float*)d_in[21];
    const float* t2_w    = (const float*)d_in[22];
    const float* t2_b    = (const float*)d_in[23];
    const float* pos2_w  = (const float*)d_in[24];
    const float* pos2_b  = (const float*)d_in[25];
    const float* gn2_g   = (const float*)d_in[26];
    const float* gn2_b   = (const float*)d_in[27];
    const float* m2a_w   = (const float*)d_in[28];
    const float* m2a_b   = (const float*)d_in[29];
    const float* m2a_g   = (const float*)d_in[30];
    const float* m2a_beta= (const float*)d_in[31];
    float* out = (float*)d_out;

    float *f1T,*f2T,*g1T,*g2T,*fn1T,*fn2T,*bufA,*bufB,*stats,*dir12,*dir21;
    unsigned *Wh,*Wl;
    int *idx12,*idx21;
    cudaGetSymbolAddress((void**)&f1T,  g_f1T);
    cudaGetSymbolAddress((void**)&f2T,  g_f2T);
    cudaGetSymbolAddress((void**)&g1T,  g_g1T);
    cudaGetSymbolAddress((void**)&g2T,  g_g2T);
    cudaGetSymbolAddress((void**)&fn1T, g_fn1T);
    cudaGetSymbolAddress((void**)&fn2T, g_fn2T);
    cudaGetSymbolAddress((void**)&idx12,g_idx12);
    cudaGetSymbolAddress((void**)&idx21,g_idx21);
    cudaGetSymbolAddress((void**)&dir12,g_dir12);
    cudaGetSymbolAddress((void**)&dir21,g_dir21);
    cudaGetSymbolAddress((void**)&bufA, g_bufA);
    cudaGetSymbolAddress((void**)&bufB, g_bufB);
    cudaGetSymbolAddress((void**)&stats,g_stats);
    cudaGetSymbolAddress((void**)&Wh,   g_Wh);
    cudaGetSymbolAddress((void**)&Wl,   g_Wl);

    k_conv1d_in<<<dim3(NN/32, BB, 4), 128>>>(feat1, feat2, t11_w, t11_b, t22_w, t22_b, stats);
    k_knn<<<dim3(NN/32, BB, 2), 128>>>(pc1, pc2);

    // ---- cross1 + cross2 merged; tail blocks pack weights ----
    k_gather<<<dim3(NN/8 + 1, BB, 2), 256>>>(idx12, dir12, f1T, f2T,
                                             idx21, dir21, g1T, g2T,
                                             pos1_w, pos1_b, bufA, stats+0*STW,
                                             m1a_w, m1b_w, m2a_w);
    k_gemm<<<POS/128, 256>>>(bufA, Wh+0*64*128, Wl+0*64*128, m1a_b,
                             stats+0*STW, gn1_g, gn1_b, bufB, stats+1*STW);
    k_gemm<<<POS/128, 256>>>(bufB, Wh+1*64*128, Wl+1*64*128, m1b_b,
                             stats+1*STW, m1a_g, m1a_beta, bufA, stats+2*STW);
    k_poolconv<<<dim3(NN/32, BB, 2), 128>>>(bufA, stats+2*STW, m1b_g, m1b_beta,
                                            t1_w, t1_b, t2_w, t2_b,
                                            out, fn1T, fn2T);

    // ---- cross 3 ----
    k_gather<<<dim3(NN/8, BB, 1), 256>>>(idx12, dir12, fn1T, fn2T,
                                         idx12, dir12, fn1T, fn2T,
                                         pos2_w, pos2_b, bufA, stats+3*STW,
                                         m1a_w, m1b_w, m2a_w);
    k_gemm<<<PP/128, 256>>>(bufA, Wh+2*64*128, Wl+2*64*128, m2a_b,
                            stats+3*STW, gn2_g, gn2_b, bufB, stats+4*STW);
    k_pool<<<dim3(NN/8, BB, 1), 128>>>(bufB, stats+4*STW, m2a_g, m2a_beta,
                                       out + 2*BB*CC*NN);
}

// round 17
// speedup vs baseline: 1.4845x; 1.0071x over previous
#include <cuda_runtime.h>
#include <cuda_bf16.h>

#define BB 2
#define NN 4096
#define CC 128
#define CIN 64
#define KK 16
#define GG 8
#define PPB (NN*KK)       // 65536 positions per batch
#define PP (BB*PPB)       // 131072 positions per cross
#define POS (2*PP)        // merged cross1+cross2 position axis
#define EPSF 1e-5f
#define CNTF 1048576.0f   // 16 * 4096 * 16 elements per (cross,b,g)
#define UPITCH 136        // smem pair-row pitch (uint32); 4*34 -> 16B-aligned rows
#define STW (2*BB*GG*2)   // stats floats per stage (2 crosses x B x G x 2)

// ---------------- scratch (device globals; no allocs allowed) ----------------
__device__ float g_f1T[BB*NN*CC];
__device__ float g_f2T[BB*NN*CC];
__device__ float g_g1T[BB*NN*CC];
__device__ float g_g2T[BB*NN*CC];
__device__ float g_fn1T[BB*NN*CC];
__device__ float g_fn2T[BB*NN*CC];
__device__ int   g_idx12[BB*NN*KK];
__device__ int   g_idx21[BB*NN*KK];
__device__ float g_dir12[BB*NN*KK*4];   // float4-padded (dx,dy,dz,0)
__device__ float g_dir21[BB*NN*KK*4];
__device__ float g_bufA[CC*POS];     // channel-major [c][cross*PP + p]
__device__ float g_bufB[CC*POS];
__device__ float g_stats[5*STW];     // per-stage (sum, sumsq)
__device__ unsigned g_Wh[3*64*128];  // packed bf16-hi pairs: [mat][kpair][orow]
__device__ unsigned g_Wl[3*64*128];  // packed bf16-lo pairs

// ---------------- helpers ----------------------------------------------------
__device__ __forceinline__ void bf16split(float v, unsigned short &h, unsigned short &l){
    __nv_bfloat16 hb = __float2bfloat16_rn(v);
    float hf = __bfloat162float(hb);
    __nv_bfloat16 lb = __float2bfloat16_rn(v - hf);
    h = *(unsigned short*)&hb;
    l = *(unsigned short*)&lb;
}
__device__ __forceinline__ unsigned pack2(unsigned short lo, unsigned short hi){
    return (unsigned)lo | ((unsigned)hi << 16);
}
__device__ __forceinline__ void mma16(float* d, const unsigned* a, unsigned b0, unsigned b1){
    asm("mma.sync.aligned.m16n8k16.row.col.f32.bf16.bf16.f32 "
        "{%0,%1,%2,%3},{%4,%5,%6,%7},{%8,%9},{%0,%1,%2,%3};"
        : "+f"(d[0]),"+f"(d[1]),"+f"(d[2]),"+f"(d[3])
        : "r"(a[0]),"r"(a[1]),"r"(a[2]),"r"(a[3]), "r"(b0),"r"(b1));
}

// -------- input 1x1 convs (+ stats zeroing folded into block 0) --------------
__global__ void k_conv1d_in(const float* __restrict__ feat1, const float* __restrict__ feat2,
                            const float* __restrict__ t11_w, const float* __restrict__ t11_b,
                            const float* __restrict__ t22_w, const float* __restrict__ t22_b,
                            float* __restrict__ stats) {
    if (blockIdx.x==0 && blockIdx.y==0 && blockIdx.z==0){
        for (int l=threadIdx.x; l<5*STW; l+=128) stats[l] = 0.f;
    }
    int job = blockIdx.z;
    int b = blockIdx.y;
    int n0 = blockIdx.x * 32;
    const float* x    = (job==0||job==3) ? feat1 : feat2;
    const float* w    = (job==0||job==2) ? t11_w : t22_w;
    const float* bias = (job==0||job==2) ? t11_b : t22_b;
    float* outp = (job==0) ? g_f1T : (job==1) ? g_f2T : (job==2) ? g_g1T : g_g2T;

    __shared__ float xs[CIN*33];
    int t = threadIdx.x;   // 128
    for (int l=t; l<CIN*32; l+=128) {
        int c=l>>5, j=l&31;
        xs[c*33+j] = x[(b*CIN+c)*NN + n0+j];
    }
    __syncthreads();
    int o = t;
    float wr[CIN];
#pragma unroll
    for (int c=0;c<CIN;c++) wr[c] = w[o*CIN+c];
    float bv = bias[o];
    for (int j=0;j<32;j++){
        float acc = bv;
#pragma unroll
        for (int c=0;c<CIN;c++) acc += wr[c]*xs[c*33+j];
        outp[(b*NN+n0+j)*CC + o] = acc;
    }
}

// ------- KNN (k=16): warp-granular 4-way split + cheap in-place insert -------
__global__ void __launch_bounds__(128) k_knn(const float* __restrict__ pc1, const float* __restrict__ pc2) {
    int dir = blockIdx.z;
    const float* pq   = (dir==0) ? pc1 : pc2;
    const float* pcnd = (dir==0) ? pc2 : pc1;
    int*   idxo = (dir==0) ? g_idx12 : g_idx21;
    float* diro = (dir==0) ? g_dir12 : g_dir21;
    int b = blockIdx.y;
    int t = threadIdx.x;
    int q  = t >> 5;        // warp = candidate quarter
    int qi = t & 31;        // query within block (same across warps)
    int n = blockIdx.x*32 + qi;

    float qx = pq[(b*3+0)*NN+n], qy = pq[(b*3+1)*NN+n], qz = pq[(b*3+2)*NN+n];
    float s1 = qx*qx + qy*qy + qz*qz;

    float bd[KK]; int bi[KK];
#pragma unroll
    for (int k=0;k<KK;k++){ bd[k]=1e30f; bi[k]=0; }
    float worst = 1e30f;

    __shared__ float4 sc[1024];
    __shared__ float md[3*32*17];
    __shared__ int   mi[3*32*17];

    for (int r=0; r<4; r++) {
        __syncthreads();
        for (int i=t; i<1024; i+=128) {
            int hs = i >> 8;
            int m = hs*1024 + r*256 + (i & 255);
            float x = pcnd[(b*3+0)*NN+m];
            float y = pcnd[(b*3+1)*NN+m];
            float z = pcnd[(b*3+2)*NN+m];
            sc[i] = make_float4(x,y,z, x*x+y*y+z*z);
        }
        __syncthreads();
        int mbase = q*1024 + r*256;
        const float4* base = &sc[q*256];
#pragma unroll 4
        for (int i=0;i<256;i++) {
            float4 c = base[i];            // warp-broadcast read
            float d = s1 + c.w - 2.f*(qx*c.x + qy*c.y + qz*c.z);
            if (d < worst) {
                int miv = mbase + i;
                bool cj = bd[KK-1] > d;
#pragma unroll
                for (int j=KK-1; j>=1; j--){
                    bool cjm = bd[j-1] > d;
                    float nv = cjm ? bd[j-1] : d;
                    int   niv = cjm ? bi[j-1] : miv;
                    bd[j] = cj ? nv  : bd[j];
                    bi[j] = cj ? niv : bi[j];
                    cj = cjm;
                }
                if (cj){ bd[0] = d; bi[0] = miv; }
                worst = bd[KK-1];
            }
        }
    }
    __syncthreads();
    if (q > 0){
#pragma unroll
        for (int k=0;k<KK;k++){
            md[((q-1)*32+qi)*17+k] = bd[k];
            mi[((q-1)*32+qi)*17+k] = bi[k];
        }
    }
    __syncthreads();
    if (q == 0){
        for (int s=0;s<3;s++){
#pragma unroll
            for (int k=0;k<KK;k++){
                float d = md[(s*32+qi)*17+k];
                if (d < worst){
                    int miv = mi[(s*32+qi)*17+k];
                    bool cj = bd[KK-1] > d;
#pragma unroll
                    for (int j=KK-1; j>=1; j--){
                        bool cjm = bd[j-1] > d;
                        float nv = cjm ? bd[j-1] : d;
                        int   niv = cjm ? bi[j-1] : miv;
                        bd[j] = cj ? nv  : bd[j];
                        bi[j] = cj ? niv : bi[j];
                        cj = cjm;
                    }
                    if (cj){ bd[0] = d; bi[0] = miv; }
                    worst = bd[KK-1];
                }
            }
        }
#pragma unroll
        for (int k=0;k<KK;k++){
            int m = bi[k];
            idxo[(b*NN+n)*KK+k] = m;
            float dx = pcnd[(b*3+0)*NN+m] - qx;
            float dy = pcnd[(b*3+1)*NN+m] - qy;
            float dz = pcnd[(b*3+2)*NN+m] - qz;
            *(float4*)&diro[((b*NN+n)*KK+k)*4] = make_float4(dx,dy,dz,0.f);
        }
    }
}

// ---- gather prologue (256 threads, k-split halves; tail blocks pack weights)
__global__ void __launch_bounds__(256) k_gather(
                         const int* __restrict__ idxA, const float* __restrict__ dirA,
                         const float* __restrict__ p1A, const float* __restrict__ p2A,
                         const int* __restrict__ idxB, const float* __restrict__ dirB,
                         const float* __restrict__ p1B, const float* __restrict__ p2B,
                         const float* __restrict__ pos_w, const float* __restrict__ pos_b,
                         float* __restrict__ X, float* __restrict__ stats,
                         const float* __restrict__ m1a, const float* __restrict__ m1b,
                         const float* __restrict__ m2a) {
    if (blockIdx.x >= NN/8){
        int j = blockIdx.z*BB + blockIdx.y;
        if (j < 3){
            const float* src = (j==0) ? m1a : (j==1) ? m1b : m2a;
            unsigned* dh = g_Wh + j*64*128;
            unsigned* dl = g_Wl + j*64*128;
            for (int l=threadIdx.x; l<64*128; l+=256){
                int kp = l >> 7, m = l & 127;
                unsigned short h0,l0,h1,l1;
                bf16split(src[m*CC + 2*kp],     h0, l0);
                bf16split(src[m*CC + 2*kp + 1], h1, l1);
                dh[l] = pack2(h0, h1);
                dl[l] = pack2(l0, l1);
            }
        }
        return;
    }
    int cross = blockIdx.z;
    const int*   idx  = cross ? idxB : idxA;
    const float* dirv = cross ? dirB : dirA;
    const float* p1T  = cross ? p1B : p1A;
    const float* p2T  = cross ? p2B : p2A;
    int b = blockIdx.y, n0 = blockIdx.x*8;
    int t = threadIdx.x;
    int c = t & 127;
    int kh = (t >> 7) * 8;     // k-half base: 0 or 8
    float pw0 = pos_w[c*3+0], pw1 = pos_w[c*3+1], pw2 = pos_w[c*3+2], pb = pos_b[c];
    __shared__ float sh[CC*33];
    float sum=0.f, sq=0.f;
    int pbase = cross*PP + b*PPB + n0*KK;
    int lane = t & 31, r0 = t >> 5;

    for (int half=0; half<4; half++){
        for (int nn=0; nn<2; nn++){
            int n = n0 + half*2 + nn;
            float p1v = p1T[(b*NN+n)*CC + c];
            const int* ip = &idx[(b*NN+n)*KK + kh];
            const float* dp0 = &dirv[((size_t)(b*NN+n)*KK + kh)*4];
#pragma unroll
            for (int k2=0;k2<8;k2++){
                int m = ip[k2];
                float4 dv = *(const float4*)&dp0[k2*4];
                float pf = pw0*dv.x + pw1*dv.y + pw2*dv.z + pb;
                float v = p2T[(b*NN+m)*CC + c] + p1v + pf;
                sum += v; sq += v*v;
                sh[c*33 + nn*KK + kh + k2] = v;
            }
        }
        __syncthreads();
        int po = pbase + half*32;
        for (int r=r0; r<CC; r+=8)
            X[(size_t)r*POS + po + lane] = sh[r*33 + lane];
        __syncthreads();
    }
#pragma unroll
    for (int off=8; off; off>>=1){
        sum += __shfl_down_sync(0xffffffffu, sum, off, 16);
        sq  += __shfl_down_sync(0xffffffffu, sq,  off, 16);
    }
    if ((t & 15)==0){
        int g = c >> 4;
        int slot = (cross*BB + b)*GG + g;
        atomicAdd(&stats[slot*2+0], sum);
        atomicAdd(&stats[slot*2+1], sq);
    }
}

// ---- fused GN+LReLU(load) -> bf16 3-term mma GEMM (double-buffered) ---------
// Chunk ch+1's LDG.128s issue before chunk ch's mma stream; split/STS deferred.
__global__ void __launch_bounds__(256, 2) k_gemm(const float* __restrict__ X,
        const unsigned* __restrict__ Whp, const unsigned* __restrict__ Wlp,
        const float* __restrict__ bias,
        const float* __restrict__ statsIn, const float* __restrict__ gamma,
        const float* __restrict__ beta, float* __restrict__ Y,
        float* __restrict__ statsOut) {
    __shared__ unsigned Xh[2][8*UPITCH], Xl[2][8*UPITCH];
    __shared__ float2 ssS[CC];

    int t = threadIdx.x;
    int pbase = blockIdx.x * 128;
    int cross = pbase >> 17;
    int b = (pbase >> 16) & 1;
    int slotB = (cross*BB + b)*GG;
    if (t < CC) {
        int g = t >> 4;
        float s = statsIn[(slotB+g)*2+0], q = statsIn[(slotB+g)*2+1];
        float mu = s / CNTF;
        float var = q / CNTF - mu*mu;
        float rstd = rsqrtf(var + EPSF);
        float scale = rstd * gamma[t];
        ssS[t] = make_float2(scale, beta[t] - mu*scale);
    }
    __syncthreads();

    int lane = t & 31, w = t >> 5;
    int gid = lane >> 2, tig = lane & 3;
    int om = (w & 3) * 32;      // warp M (output-channel) base
    int pn = (w >> 2) * 64;     // warp N (position) base within the 128 tile

    // staging unit: one (k-pair, col4) per thread
    int sk2 = t >> 5;           // 0..7
    int scol = (t & 31) * 4;    // 0,4,...,124

    float acc[2][8][4];
#pragma unroll
    for (int i=0;i<2;i++)
#pragma unroll
        for (int j=0;j<8;j++)
#pragma unroll
            for (int r=0;r<4;r++) acc[i][j][r]=0.f;

    // split+pack one staged pair of float4s and store into buffer `buf`
    auto stage_store = [&](int buf, float4 xa, float4 xb, float2 s0, float2 s1){
        float a0 = xa.x*s0.x + s0.y, a1 = xa.y*s0.x + s0.y;
        float a2 = xa.z*s0.x + s0.y, a3 = xa.w*s0.x + s0.y;
        float b0 = xb.x*s1.x + s1.y, b1 = xb.y*s1.x + s1.y;
        float b2 = xb.z*s1.x + s1.y, b3 = xb.w*s1.x + s1.y;
        a0 = (a0>=0.f)?a0:0.1f*a0; a1 = (a1>=0.f)?a1:0.1f*a1;
        a2 = (a2>=0.f)?a2:0.1f*a2; a3 = (a3>=0.f)?a3:0.1f*a3;
        b0 = (b0>=0.f)?b0:0.1f*b0; b1 = (b1>=0.f)?b1:0.1f*b1;
        b2 = (b2>=0.f)?b2:0.1f*b2; b3 = (b3>=0.f)?b3:0.1f*b3;
        unsigned short ha0,la0,ha1,la1,ha2,la2,ha3,la3;
        unsigned short hb0,lb0,hb1,lb1,hb2,lb2,hb3,lb3;
        bf16split(a0,ha0,la0); bf16split(a1,ha1,la1);
        bf16split(a2,ha2,la2); bf16split(a3,ha3,la3);
        bf16split(b0,hb0,lb0); bf16split(b1,hb1,lb1);
        bf16split(b2,hb2,lb2); bf16split(b3,hb3,lb3);
        uint4 vh = make_uint4(pack2(ha0,hb0), pack2(ha1,hb1),
                              pack2(ha2,hb2), pack2(ha3,hb3));
        uint4 vl = make_uint4(pack2(la0,lb0), pack2(la1,lb1),
                              pack2(la2,lb2), pack2(la3,lb3));
        *(uint4*)&Xh[buf][sk2*UPITCH + scol] = vh;
        *(uint4*)&Xl[buf][sk2*UPITCH + scol] = vl;
    };

    // stage chunk 0
    {
        int kk = sk2*2;
        float4 xa = *(const float4*)&X[(size_t)kk*POS + pbase + scol];
        float4 xb = *(const float4*)&X[(size_t)(kk+1)*POS + pbase + scol];
        stage_store(0, xa, xb, ssS[kk], ssS[kk+1]);
    }
    __syncthreads();

    for (int ch=0; ch<8; ch++) {
        int cur = ch & 1;
        int kc8 = ch*8;
        // prefetch next chunk's raw data (LDG issues before mma stream)
        float4 pxa, pxb;
        if (ch < 7){
            int kk = ((ch+1)*8 + sk2)*2;
            pxa = *(const float4*)&X[(size_t)kk*POS + pbase + scol];
            pxb = *(const float4*)&X[(size_t)(kk+1)*POS + pbase + scol];
        }

        unsigned ah[2][4], al[2][4];
#pragma unroll
        for (int tm=0;tm<2;tm++){
            int mrow = om + tm*16 + gid;
            const unsigned* wh0 = &Whp[(kc8+tig)*128];
            const unsigned* wh4 = &Whp[(kc8+tig+4)*128];
            const unsigned* wl0 = &Wlp[(kc8+tig)*128];
            const unsigned* wl4 = &Wlp[(kc8+tig+4)*128];
            ah[tm][0] = __ldg(wh0 + mrow);
            ah[tm][1] = __ldg(wh0 + mrow + 8);
            ah[tm][2] = __ldg(wh4 + mrow);
            ah[tm][3] = __ldg(wh4 + mrow + 8);
            al[tm][0] = __ldg(wl0 + mrow);
            al[tm][1] = __ldg(wl0 + mrow + 8);
            al[tm][2] = __ldg(wl4 + mrow);
            al[tm][3] = __ldg(wl4 + mrow + 8);
        }
#pragma unroll
        for (int tn=0;tn<8;tn++){
            int p = pn + tn*8 + gid;
            unsigned bh0 = Xh[cur][tig*UPITCH + p];
            unsigned bh1 = Xh[cur][(tig+4)*UPITCH + p];
            unsigned bl0 = Xl[cur][tig*UPITCH + p];
            unsigned bl1 = Xl[cur][(tig+4)*UPITCH + p];
            mma16(acc[0][tn], ah[0], bh0, bh1);
            mma16(acc[1][tn], ah[1], bh0, bh1);
            mma16(acc[0][tn], al[0], bh0, bh1);
            mma16(acc[1][tn], al[1], bh0, bh1);
            mma16(acc[0][tn], ah[0], bl0, bl1);
            mma16(acc[1][tn], ah[1], bl0, bl1);
        }
        if (ch < 7){
            int kk = ((ch+1)*8 + sk2)*2;
            stage_store(1-cur, pxa, pxb, ssS[kk], ssS[kk+1]);
        }
        __syncthreads();
    }

    // epilogue: bias, stores, GN stats
    float ssum[2] = {0.f, 0.f}, sq[2] = {0.f, 0.f};
#pragma unroll
    for (int tm=0;tm<2;tm++){
        int row0 = om + tm*16 + gid;
        float bv0 = bias[row0], bv1 = bias[row0+8];
#pragma unroll
        for (int tn=0;tn<8;tn++){
            float y0 = acc[tm][tn][0] + bv0;
            float y1 = acc[tm][tn][1] + bv0;
            float y2 = acc[tm][tn][2] + bv1;
            float y3 = acc[tm][tn][3] + bv1;
            ssum[tm] += (y0+y1)+(y2+y3);
            sq[tm]   += (y0*y0+y1*y1)+(y2*y2+y3*y3);
            int col = pbase + pn + tn*8 + tig*2;
            *(float2*)&Y[(size_t)row0*POS + col]     = make_float2(y0,y1);
            *(float2*)&Y[(size_t)(row0+8)*POS + col] = make_float2(y2,y3);
        }
    }
#pragma unroll
    for (int off=16; off; off>>=1){
        ssum[0] += __shfl_down_sync(0xffffffffu, ssum[0], off);
        sq[0]   += __shfl_down_sync(0xffffffffu, sq[0],   off);
        ssum[1] += __shfl_down_sync(0xffffffffu, ssum[1], off);
        sq[1]   += __shfl_down_sync(0xffffffffu, sq[1],   off);
    }
    if (lane == 0){
        int gb = (w & 3)*2;
        atomicAdd(&statsOut[(slotB+gb)*2+0],   ssum[0]);
        atomicAdd(&statsOut[(slotB+gb)*2+1],   sq[0]);
        atomicAdd(&statsOut[(slotB+gb+1)*2+0], ssum[1]);
        atomicAdd(&statsOut[(slotB+gb+1)*2+1], sq[1]);
    }
}

// ---- fused GN+LReLU + max-pool + trailing 1x1 conv (crosses 1/2) ------------
__global__ void __launch_bounds__(128) k_poolconv(const float* __restrict__ Y,
                          const float* __restrict__ statsIn,
                          const float* __restrict__ gamma, const float* __restrict__ beta,
                          const float* __restrict__ t1_w, const float* __restrict__ t1_b,
                          const float* __restrict__ t2_w, const float* __restrict__ t2_b,
                          float* __restrict__ outBase, float* __restrict__ fn1T,
                          float* __restrict__ fn2T) {
    int cross = blockIdx.z;
    int b = blockIdx.y;
    int t = threadIdx.x;
    int n0 = blockIdx.x*32;
    int p0 = cross*PP + b*PPB + n0*KK;      // 512 positions
    const float* w    = cross ? t2_w : t1_w;
    const float* bias = cross ? t2_b : t1_b;
    float* outCM = outBase + (size_t)cross*BB*CC*NN;
    float* fnT   = cross ? fn2T : fn1T;
    int slotB = (cross*BB + b)*GG;

    __shared__ float2 ssS[CC];
    __shared__ float xs[CC*36];
    if (t < CC){
        int g = t >> 4;
        float s = statsIn[(slotB+g)*2+0], q = statsIn[(slotB+g)*2+1];
        float mu = s / CNTF;
        float var = q / CNTF - mu*mu;
        float rstd = rsqrtf(var + EPSF);
        float scale = rstd * gamma[t];
        ssS[t] = make_float2(scale, beta[t] - mu*scale);
    }
    __syncthreads();

    int kk = t & 15;
#pragma unroll 2
    for (int c=0;c<CC;c++){
        float2 ss = ssS[c];
        const float* yrow = &Y[(size_t)c*POS + p0];
#pragma unroll
        for (int j=0;j<4;j++){
            float v = yrow[t + j*128]*ss.x + ss.y;
            v = (v>=0.f) ? v : 0.1f*v;
#pragma unroll
            for (int off=8; off; off>>=1)
                v = fmaxf(v, __shfl_xor_sync(0xffffffffu, v, off, 16));
            if (kk == 0) xs[c*36 + ((t + j*128)>>4)] = v;
        }
    }
    __syncthreads();

    int o = t;
    float acc[32];
    float bv = bias[o];
#pragma unroll
    for (int j=0;j<32;j++) acc[j]=bv;
    for (int cc=0; cc<4; cc++){
        float wr[32];
#pragma unroll
        for (int c2=0;c2<32;c2++) wr[c2] = w[o*CC + cc*32 + c2];
#pragma unroll
        for (int c2=0;c2<32;c2++){
            const float* xrow = &xs[(cc*32+c2)*36];
            float wv = wr[c2];
#pragma unroll
            for (int j4=0;j4<8;j4++){
                float4 xv = *(const float4*)&xrow[j4*4];
                acc[j4*4+0]+=wv*xv.x; acc[j4*4+1]+=wv*xv.y;
                acc[j4*4+2]+=wv*xv.z; acc[j4*4+3]+=wv*xv.w;
            }
        }
    }
#pragma unroll
    for (int j=0;j<32;j++) fnT[(b*NN+n0+j)*CC + o] = acc[j];
    __syncthreads();
#pragma unroll
    for (int j=0;j<32;j++) xs[o*36+j] = acc[j];
    __syncthreads();
    int lane = t & 31, r0 = t >> 5;
    for (int r=r0; r<CC; r+=4)
        outCM[(b*CC+r)*NN + n0 + lane] = xs[r*36+lane];
}

// ------- GN+LReLU apply + max-pool over K (cross3 epilogue) ------------------
__global__ void __launch_bounds__(128) k_pool(const float* __restrict__ Y,
                       const float* __restrict__ statsIn,
                       const float* __restrict__ gamma, const float* __restrict__ beta,
                       float* __restrict__ outCM) {
    int b = blockIdx.y;
    int t = threadIdx.x;
    int p0 = b*PPB + blockIdx.x*128;
    int nb = blockIdx.x*8 + (t >> 4);
    int kk = t & 15;
    int slotB = b*GG;
    __shared__ float2 ssS[CC];
    if (t < CC){
        int g = t >> 4;
        float s = statsIn[(slotB+g)*2+0], q = statsIn[(slotB+g)*2+1];
        float mu = s / CNTF;
        float var = q / CNTF - mu*mu;
        float rstd = rsqrtf(var + EPSF);
        float scale = rstd * gamma[t];
        ssS[t] = make_float2(scale, beta[t] - mu*scale);
    }
    __syncthreads();
#pragma unroll 4
    for (int c=0;c<CC;c++){
        float2 ss = ssS[c];
        float v = Y[(size_t)c*POS + p0 + t]*ss.x + ss.y;
        v = (v>=0.f) ? v : 0.1f*v;
#pragma unroll
        for (int off=8; off; off>>=1)
            v = fmaxf(v, __shfl_xor_sync(0xffffffffu, v, off, 16));
        if (kk == 0)
            outCM[(b*CC+c)*NN + nb] = v;
    }
}

// ---------------- host orchestration ----------------------------------------
extern "C" void kernel_launch(void* const* d_in, const int* in_sizes, int n_in,
                              void* d_out, int out_size) {
    const float* pc1     = (const float*)d_in[0];
    const float* pc2     = (const float*)d_in[1];
    const float* feat1   = (const float*)d_in[2];
    const float* feat2   = (const float*)d_in[3];
    const float* t11_w   = (const float*)d_in[4];
    const float* t11_b   = (const float*)d_in[5];
    const float* t22_w   = (const float*)d_in[6];
    const float* t22_b   = (const float*)d_in[7];
    const float* pos1_w  = (const float*)d_in[8];
    const float* pos1_b  = (const float*)d_in[9];
    const float* gn1_g   = (const float*)d_in[10];
    const float* gn1_b   = (const float*)d_in[11];
    const float* m1a_w   = (const float*)d_in[12];
    const float* m1a_b   = (const float*)d_in[13];
    const float* m1a_g   = (const float*)d_in[14];
    const float* m1a_beta= (const float*)d_in[15];
    const float* m1b_w   = (const float*)d_in[16];
    const float* m1b_b   = (const float*)d_in[17];
    const float* m1b_g   = (const float*)d_in[18];
    const float* m1b_beta= (const float*)d_in[19];
    const float* t1_w    = (const float*)d_in[20];
    const float* t1_b    = (const float*)d_in[21];
    const float* t2_w    = (const float*)d_in[22];
    const float* t2_b    = (const float*)d_in[23];
    const float* pos2_w  = (const float*)d_in[24];
    const float* pos2_b  = (const float*)d_in[25];
    const float* gn2_g   = (const float*)d_in[26];
    const float* gn2_b   = (const float*)d_in[27];
    const float* m2a_w   = (const float*)d_in[28];
    const float* m2a_b   = (const float*)d_in[29];
    const float* m2a_g   = (const float*)d_in[30];
    const float* m2a_beta= (const float*)d_in[31];
    float* out = (float*)d_out;

    float *f1T,*f2T,*g1T,*g2T,*fn1T,*fn2T,*bufA,*bufB,*stats,*dir12,*dir21;
    unsigned *Wh,*Wl;
    int *idx12,*idx21;
    cudaGetSymbolAddress((void**)&f1T,  g_f1T);
    cudaGetSymbolAddress((void**)&f2T,  g_f2T);
    cudaGetSymbolAddress((void**)&g1T,  g_g1T);
    cudaGetSymbolAddress((void**)&g2T,  g_g2T);
    cudaGetSymbolAddress((void**)&fn1T, g_fn1T);
    cudaGetSymbolAddress((void**)&fn2T, g_fn2T);
    cudaGetSymbolAddress((void**)&idx12,g_idx12);
    cudaGetSymbolAddress((void**)&idx21,g_idx21);
    cudaGetSymbolAddress((void**)&dir12,g_dir12);
    cudaGetSymbolAddress((void**)&dir21,g_dir21);
    cudaGetSymbolAddress((void**)&bufA, g_bufA);
    cudaGetSymbolAddress((void**)&bufB, g_bufB);
    cudaGetSymbolAddress((void**)&stats,g_stats);
    cudaGetSymbolAddress((void**)&Wh,   g_Wh);
    cudaGetSymbolAddress((void**)&Wl,   g_Wl);

    k_conv1d_in<<<dim3(NN/32, BB, 4), 128>>>(feat1, feat2, t11_w, t11_b, t22_w, t22_b, stats);
    k_knn<<<dim3(NN/32, BB, 2), 128>>>(pc1, pc2);

    // ---- cross1 + cross2 merged; tail blocks pack weights ----
    k_gather<<<dim3(NN/8 + 1, BB, 2), 256>>>(idx12, dir12, f1T, f2T,
                                             idx21, dir21, g1T, g2T,
                                             pos1_w, pos1_b, bufA, stats+0*STW,
                                             m1a_w, m1b_w, m2a_w);
    k_gemm<<<POS/128, 256>>>(bufA, Wh+0*64*128, Wl+0*64*128, m1a_b,
                             stats+0*STW, gn1_g, gn1_b, bufB, stats+1*STW);
    k_gemm<<<POS/128, 256>>>(bufB, Wh+1*64*128, Wl+1*64*128, m1b_b,
                             stats+1*STW, m1a_g, m1a_beta, bufA, stats+2*STW);
    k_poolconv<<<dim3(NN/32, BB, 2), 128>>>(bufA, stats+2*STW, m1b_g, m1b_beta,
                                            t1_w, t1_b, t2_w, t2_b,
                                            out, fn1T, fn2T);

    // ---- cross 3 ----
    k_gather<<<dim3(NN/8, BB, 1), 256>>>(idx12, dir12, fn1T, fn2T,
                                         idx12, dir12, fn1T, fn2T,
                                         pos2_w, pos2_b, bufA, stats+3*STW,
                                         m1a_w, m1b_w, m2a_w);
    k_gemm<<<PP/128, 256>>>(bufA, Wh+2*64*128, Wl+2*64*128, m2a_b,
                            stats+3*STW, gn2_g, gn2_b, bufB, stats+4*STW);
    k_pool<<<dim3(NN/8, BB, 1), 128>>>(bufB, stats+4*STW, m2a_g, m2a_beta,
                                       out + 2*BB*CC*NN);
}